// round 9
// baseline (speedup 1.0000x reference)
#include <cuda_runtime.h>
#include <cuda_bf16.h>
#include <cstdint>

#define DINLINE __device__ __forceinline__

constexpr int B_  = 2;
constexpr int S_  = 2048;
constexpr int D_  = 1024;
constexpr int H_  = 16;
constexpr int DK_ = 64;

constexpr size_t NQKV = (size_t)B_ * H_ * S_ * DK_;   // 4M elems
constexpr size_t XSZ  = (size_t)4096 * 1024;          // 4M
constexpr size_t WSZ  = (size_t)1024 * 1024;          // 1M

// ---------------- global scratch ----------------
__device__ __nv_bfloat16 g_xh[3 * XSZ], g_xl[3 * XSZ];     // q,k,v inputs split
__device__ __nv_bfloat16 g_wh[4 * WSZ], g_wl[4 * WSZ];     // wq,wk,wv,wo split
__device__ __nv_bfloat16 g_h[3 * NQKV], g_l[3 * NQKV];     // Q,K,V proj [B,H,S,DK]
__device__ __nv_bfloat16 g_ch[XSZ], g_cl[XSZ];             // attn context split

// ---------------- helpers ----------------
DINLINE unsigned packh(__nv_bfloat16 a, __nv_bfloat16 b) {
    __nv_bfloat162 v; v.x = a; v.y = b;
    return *reinterpret_cast<unsigned*>(&v);
}
DINLINE void splitf(float x, __nv_bfloat16& h, __nv_bfloat16& l) {
    h = __float2bfloat16(x);
    l = __float2bfloat16(x - __bfloat162float(h));
}
DINLINE void mma16816(float* c, const unsigned* a, unsigned b0, unsigned b1) {
    asm volatile(
        "mma.sync.aligned.m16n8k16.row.col.f32.bf16.bf16.f32 "
        "{%0,%1,%2,%3},{%4,%5,%6,%7},{%8,%9},{%0,%1,%2,%3};\n"
        : "+f"(c[0]), "+f"(c[1]), "+f"(c[2]), "+f"(c[3])
        : "r"(a[0]), "r"(a[1]), "r"(a[2]), "r"(a[3]), "r"(b0), "r"(b1));
}
DINLINE unsigned smem_u32(const void* p) {
    unsigned a;
    asm("{.reg .u64 t; cvta.to.shared.u64 t, %1; cvt.u32.u64 %0, t;}" : "=r"(a) : "l"(p));
    return a;
}
DINLINE void ldsm_x4(unsigned* r, unsigned addr) {
    asm volatile("ldmatrix.sync.aligned.m8n8.x4.shared.b16 {%0,%1,%2,%3}, [%4];"
                 : "=r"(r[0]), "=r"(r[1]), "=r"(r[2]), "=r"(r[3]) : "r"(addr));
}
DINLINE void ldsm_x4t(unsigned* r, unsigned addr) {
    asm volatile("ldmatrix.sync.aligned.m8n8.x4.trans.shared.b16 {%0,%1,%2,%3}, [%4];"
                 : "=r"(r[0]), "=r"(r[1]), "=r"(r[2]), "=r"(r[3]) : "r"(addr));
}

#define CP_ASYNC16(dst, src) \
    asm volatile("cp.async.cg.shared.global [%0], [%1], 16;\n" :: "r"(dst), "l"(src))
#define CP_COMMIT()  asm volatile("cp.async.commit_group;\n")
#define CP_WAIT0()   asm volatile("cp.async.wait_group 0;\n")
#define CP_WAIT1()   asm volatile("cp.async.wait_group 1;\n")

// ============================================================================
// convert: f32 inputs/weights -> bf16 hi/lo global buffers
// ============================================================================
__global__ void __launch_bounds__(256) convert_kernel(
    const float* __restrict__ q, const float* __restrict__ k, const float* __restrict__ v,
    const float* __restrict__ wq, const float* __restrict__ wk,
    const float* __restrict__ wv, const float* __restrict__ wo)
{
    size_t i = ((size_t)blockIdx.x * 256 + threadIdx.x) * 4;
    const float* src;
    __nv_bfloat16 *dh, *dl;
    size_t off;
    if (i < (size_t)3 * XSZ) {
        int z = (int)(i / XSZ);
        off = i - (size_t)z * XSZ;
        src = (z == 0) ? q : (z == 1) ? k : v;
        dh = g_xh + (size_t)z * XSZ; dl = g_xl + (size_t)z * XSZ;
    } else {
        size_t j = i - (size_t)3 * XSZ;
        int z = (int)(j / WSZ);
        off = j - (size_t)z * WSZ;
        src = (z == 0) ? wq : (z == 1) ? wk : (z == 2) ? wv : wo;
        dh = g_wh + (size_t)z * WSZ; dl = g_wl + (size_t)z * WSZ;
    }
    float4 val = *(const float4*)(src + off);
    __nv_bfloat16 h0, l0, h1, l1, h2, l2, h3, l3;
    splitf(val.x, h0, l0); splitf(val.y, h1, l1);
    splitf(val.z, h2, l2); splitf(val.w, h3, l3);
    uint2 uh = { packh(h0, h1), packh(h2, h3) };
    uint2 ul = { packh(l0, l1), packh(l2, l3) };
    *(uint2*)(dh + off) = uh;
    *(uint2*)(dl + off) = ul;
}

// ============================================================================
// GEMM: Y[4096,1024] = X @ W^T + b, pre-split bf16 hi/lo, 3-term.
// PERSISTENT CTAs: grid = 296 (2/SM x 148 SMs); each CTA strides over tiles.
// Tile 128x128, 256 threads (8 warps, warptile 32x64), BK=32.
// 3-stage cp.async pipeline, ONE __syncthreads per K-iteration.
// Body order: ldsm(kk2=0) -> cp.async next stage -> mma(0) -> ldsm(1) -> mma(1).
// XOR-swizzled smem chunks (conflict-free, no pad). Stage=32KB, 3 stages=96KB.
// Inter-tile smem hazard: last compute reads stage 2; new prologue writes
// stages 0,1 (disjoint); kt=0 top barrier orders the rest. No extra barrier.
// MODE 0: tiles 0..767 (z = tid>>8); hi/lo bf16 out.  MODE 1: 256 tiles, f32.
// ============================================================================
constexpr int G_ARR_B   = 128 * 64;            // 8192 bytes per array
constexpr int G_STAGE_B = 4 * G_ARR_B;         // 32768 bytes per stage
constexpr int GEMM_SMEM = 3 * G_STAGE_B;       // 98304 bytes
constexpr int GEMM_GRID0 = 296;                // 148 SMs x 2 CTAs

template<int MODE>
__global__ void __launch_bounds__(256, 2) gemm_kernel(
    const __nv_bfloat16* __restrict__ Ahg, const __nv_bfloat16* __restrict__ Alg,
    const __nv_bfloat16* __restrict__ Whg, const __nv_bfloat16* __restrict__ Wlg,
    const float* __restrict__ b0p, const float* __restrict__ b1p, const float* __restrict__ b2p,
    __nv_bfloat16* __restrict__ Yh, __nv_bfloat16* __restrict__ Yl,
    float* __restrict__ Yf)
{
    extern __shared__ __nv_bfloat16 gsm[];
    const unsigned smb = smem_u32(gsm);

    const int t    = threadIdx.x;
    const int w    = t >> 5;
    const int lane = t & 31;
    const int g    = lane >> 2;
    const int tg   = lane & 3;
    const int lm   = lane >> 3;   // ldmatrix matrix id (0..3)
    const int lr   = lane & 7;    // ldmatrix row-in-matrix
    const int wm   = w >> 1;      // 0..3
    const int wn   = w & 1;       // 0..1

    // tile-independent ldmatrix per-lane bases
    unsigned aoff[2], axor[2], boff[4], bxor[4];
    const unsigned aC = (unsigned)(lm >> 1);
    const unsigned bC = (unsigned)(lm & 1);
#pragma unroll
    for (int mi = 0; mi < 2; mi++) {
        int r = wm * 32 + mi * 16 + ((lm & 1) << 3) + lr;
        aoff[mi] = (unsigned)r * 64u;
        axor[mi] = (unsigned)((r >> 1) & 3);
    }
#pragma unroll
    for (int p = 0; p < 4; p++) {
        int r = wn * 64 + p * 16 + ((lm >> 1) << 3) + lr;
        boff[p] = (unsigned)r * 64u;
        bxor[p] = (unsigned)((r >> 1) & 3);
    }

    const int NT = (MODE == 0) ? 768 : 256;

    for (int tid = blockIdx.x; tid < NT; tid += gridDim.x) {
        const int z   = (MODE == 0) ? (tid >> 8) : 0;
        const int rem = tid & 255;
        const int m0  = (rem >> 3) * 128;
        const int n0  = (rem & 7) * 128;

        const __nv_bfloat16* Ah = Ahg + (size_t)z * XSZ;
        const __nv_bfloat16* Al = Alg + (size_t)z * XSZ;
        const __nv_bfloat16* Bh = Whg + (size_t)z * WSZ;
        const __nv_bfloat16* Bl = Wlg + (size_t)z * WSZ;
        const float* bias = (z == 0) ? b0p : (z == 1) ? b1p : b2p;

        float acc[2][8][4];
#pragma unroll
        for (int mi = 0; mi < 2; mi++)
#pragma unroll
            for (int ni = 0; ni < 8; ni++)
#pragma unroll
                for (int j = 0; j < 4; j++) acc[mi][ni][j] = 0.f;

        auto issue_stage = [&](int kt, int stg) {
            const unsigned base = (unsigned)(stg * G_STAGE_B);
#pragma unroll
            for (int i = 0; i < 8; i++) {
                int id = t + i * 256;
                int a_ = id >> 9;                 // array 0..3
                int cid = id & 511;
                int row = cid >> 2, c = cid & 3;
                const __nv_bfloat16* gp =
                    (a_ == 0) ? Ah : (a_ == 1) ? Al : (a_ == 2) ? Bh : Bl;
                const int r0 = (a_ < 2) ? m0 : n0;
                unsigned dst = smb + base + (unsigned)a_ * G_ARR_B
                             + (unsigned)row * 64u
                             + ((unsigned)(c ^ ((row >> 1) & 3)) << 4);
                CP_ASYNC16(dst, gp + (size_t)(r0 + row) * 1024 + (size_t)kt * 32 + c * 8);
            }
            CP_COMMIT();
        };

        issue_stage(0, 0);
        issue_stage(1, 1);

        for (int kt = 0; kt < 32; kt++) {
            if (kt < 31) CP_WAIT1(); else CP_WAIT0();
            __syncthreads();          // tile kt ready AND compute of kt-1 done

            const unsigned sb = smb + (unsigned)((kt % 3) * G_STAGE_B);
            unsigned ah[2][4], al[2][4], bh[4][4], bl[4][4];

            // ---- kk2 = 0 fragment loads ----
#pragma unroll
            for (int mi = 0; mi < 2; mi++) {
                unsigned cidx = (aC ^ axor[mi]) << 4;
                ldsm_x4(ah[mi], sb + aoff[mi] + cidx);
                ldsm_x4(al[mi], sb + G_ARR_B + aoff[mi] + cidx);
            }
#pragma unroll
            for (int p = 0; p < 4; p++) {
                unsigned cidx = (bC ^ bxor[p]) << 4;
                ldsm_x4(bh[p], sb + 2 * G_ARR_B + boff[p] + cidx);
                ldsm_x4(bl[p], sb + 3 * G_ARR_B + boff[p] + cidx);
            }

            // overlap: issue next stage while kk2=0 MMAs run
            if (kt + 2 < 32) issue_stage(kt + 2, (kt + 2) % 3);

            // ---- kk2 = 0 MMAs ----
#pragma unroll
            for (int ni = 0; ni < 8; ni++) {
                const int p = ni >> 1, ix = (ni & 1) * 2;
                unsigned b0h = bh[p][ix], b1h = bh[p][ix + 1];
                unsigned b0l = bl[p][ix], b1l = bl[p][ix + 1];
#pragma unroll
                for (int mi = 0; mi < 2; mi++) {
                    mma16816(acc[mi][ni], ah[mi], b0h, b1h);
                    mma16816(acc[mi][ni], ah[mi], b0l, b1l);
                    mma16816(acc[mi][ni], al[mi], b0h, b1h);
                }
            }

            // ---- kk2 = 1 fragment loads ----
#pragma unroll
            for (int mi = 0; mi < 2; mi++) {
                unsigned cidx = ((2u + aC) ^ axor[mi]) << 4;
                ldsm_x4(ah[mi], sb + aoff[mi] + cidx);
                ldsm_x4(al[mi], sb + G_ARR_B + aoff[mi] + cidx);
            }
#pragma unroll
            for (int p = 0; p < 4; p++) {
                unsigned cidx = ((2u + bC) ^ bxor[p]) << 4;
                ldsm_x4(bh[p], sb + 2 * G_ARR_B + boff[p] + cidx);
                ldsm_x4(bl[p], sb + 3 * G_ARR_B + boff[p] + cidx);
            }

            // ---- kk2 = 1 MMAs ----
#pragma unroll
            for (int ni = 0; ni < 8; ni++) {
                const int p = ni >> 1, ix = (ni & 1) * 2;
                unsigned b0h = bh[p][ix], b1h = bh[p][ix + 1];
                unsigned b0l = bl[p][ix], b1l = bl[p][ix + 1];
#pragma unroll
                for (int mi = 0; mi < 2; mi++) {
                    mma16816(acc[mi][ni], ah[mi], b0h, b1h);
                    mma16816(acc[mi][ni], ah[mi], b0l, b1l);
                    mma16816(acc[mi][ni], al[mi], b0h, b1h);
                }
            }
        }

        // ---- epilogue ----
        const size_t zoff = (size_t)z * NQKV;
#pragma unroll
        for (int mi = 0; mi < 2; mi++) {
#pragma unroll
            for (int ni = 0; ni < 8; ni++) {
                int r = m0 + wm * 32 + mi * 16 + g;
                int c = n0 + wn * 64 + ni * 8 + tg * 2;
                float b0 = bias[c], b1 = bias[c + 1];
                float v00 = acc[mi][ni][0] + b0;
                float v01 = acc[mi][ni][1] + b1;
                float v10 = acc[mi][ni][2] + b0;
                float v11 = acc[mi][ni][3] + b1;
                if (MODE == 0) {
                    int bb = r >> 11, ss = r & 2047;
                    int hh = c >> 6, d = c & 63;
                    size_t i0 = zoff + ((size_t)(bb * H_ + hh) * S_ + ss) * DK_ + d;
                    size_t i1 = zoff + ((size_t)(bb * H_ + hh) * S_ + (ss + 8)) * DK_ + d;
                    __nv_bfloat16 h0, l0, h1, l1;
                    splitf(v00, h0, l0); splitf(v01, h1, l1);
                    *(unsigned*)&Yh[i0] = packh(h0, h1);
                    *(unsigned*)&Yl[i0] = packh(l0, l1);
                    splitf(v10, h0, l0); splitf(v11, h1, l1);
                    *(unsigned*)&Yh[i1] = packh(h0, h1);
                    *(unsigned*)&Yl[i1] = packh(l0, l1);
                } else {
                    Yf[(size_t)r * 1024 + c]           = v00;
                    Yf[(size_t)r * 1024 + c + 1]       = v01;
                    Yf[(size_t)(r + 8) * 1024 + c]     = v10;
                    Yf[(size_t)(r + 8) * 1024 + c + 1] = v11;
                }
            }
        }
    }
}

// ============================================================================
// Flash attention (causal), DK=64, Q-tile 128 (8 warps x 16 rows), KV-tile 64.
// (unchanged from R8 passing version)
// ============================================================================
constexpr int ALD = 72;
constexpr int A_ARR = 64 * ALD;         // 4608 elems per array
constexpr int STAGE = 4 * A_ARR;        // Kh,Kl,Vh,Vl
constexpr int ATTN_SMEM = 2 * STAGE * 2;

__global__ void __launch_bounds__(256, 1) attn_kernel(
    const __nv_bfloat16* __restrict__ Gh, const __nv_bfloat16* __restrict__ Gl,
    __nv_bfloat16* __restrict__ Ch, __nv_bfloat16* __restrict__ Cl)
{
    extern __shared__ __nv_bfloat16 sm[];

    const int qt   = (int)gridDim.x - 1 - (int)blockIdx.x;  // heavy first
    const int bh   = blockIdx.y;
    const int t    = threadIdx.x;
    const int w    = t >> 5;
    const int lane = t & 31;
    const int g    = lane >> 2;
    const int tg   = lane & 3;
    const int lm   = lane >> 3;
    const int lr   = lane & 7;

    const size_t hb = (size_t)bh * S_ * DK_;
    const __nv_bfloat16* Qhb = Gh + hb;
    const __nv_bfloat16* Qlb = Gl + hb;
    const __nv_bfloat16* Khb = Gh + NQKV + hb;
    const __nv_bfloat16* Klb = Gl + NQKV + hb;
    const __nv_bfloat16* Vhb = Gh + 2 * NQKV + hb;
    const __nv_bfloat16* Vlb = Gl + 2 * NQKV + hb;

    const unsigned smb = smem_u32(sm);
    const float NEG = -1e30f;

    const int kbase = lr * ALD + (lm << 3);
    const int vbase = (((lm & 1) << 3) + lr) * ALD + ((lm >> 1) << 3);

    unsigned qh[4][4], ql[4][4];
    {
        size_t r0 = (size_t)(qt * 128 + w * 16 + g) * DK_;
        size_t r1 = r0 + 8 * DK_;
#pragma unroll
        for (int kk = 0; kk < 4; kk++) {
            int c = kk * 16 + tg * 2;
            qh[kk][0] = *(const unsigned*)&Qhb[r0 + c];
            qh[kk][1] = *(const unsigned*)&Qhb[r1 + c];
            qh[kk][2] = *(const unsigned*)&Qhb[r0 + c + 8];
            qh[kk][3] = *(const unsigned*)&Qhb[r1 + c + 8];
            ql[kk][0] = *(const unsigned*)&Qlb[r0 + c];
            ql[kk][1] = *(const unsigned*)&Qlb[r1 + c];
            ql[kk][2] = *(const unsigned*)&Qlb[r0 + c + 8];
            ql[kk][3] = *(const unsigned*)&Qlb[r1 + c + 8];
        }
    }

    auto issue_tile = [&](int kt, int stg) {
#pragma unroll
        for (int i = 0; i < 8; i++) {
            int id = t + i * 256;
            int a_ = id >> 9;
            int cid = id & 511;
            int row = cid >> 3, seg = cid & 7;
            const __nv_bfloat16* gp =
                (a_ == 0) ? Khb : (a_ == 1) ? Klb : (a_ == 2) ? Vhb : Vlb;
            unsigned dst = smb + (unsigned)(stg * STAGE + a_ * A_ARR + row * ALD + seg * 8) * 2;
            CP_ASYNC16(dst, gp + (size_t)(kt * 64 + row) * DK_ + seg * 8);
        }
        CP_COMMIT();
    };

    float m0v = NEG, m1v = NEG, l0v = 0.f, l1v = 0.f;
    float o[8][4];
#pragma unroll
    for (int ni = 0; ni < 8; ni++)
#pragma unroll
        for (int j = 0; j < 4; j++) o[ni][j] = 0.f;

    const int ktmax = 2 * qt + 2;
    issue_tile(0, 0);

    for (int kt = 0; kt < ktmax; kt++) {
        const int s = kt & 1;
        CP_WAIT0();
        __syncthreads();

        if (kt + 1 < ktmax) issue_tile(kt + 1, s ^ 1);

        const unsigned sb = (unsigned)(s * STAGE);

        float sc_[8][4];
#pragma unroll
        for (int ni = 0; ni < 8; ni++) {
#pragma unroll
            for (int j = 0; j < 4; j++) sc_[ni][j] = 0.f;
            unsigned kh[2][4], kl[2][4];
#pragma unroll
            for (int q = 0; q < 2; q++) {
                unsigned off = sb + ni * 8 * ALD + q * 32 + kbase;
                ldsm_x4(kh[q], smb + off * 2);
                ldsm_x4(kl[q], smb + (off + A_ARR) * 2);
            }
#pragma unroll
            for (int kk = 0; kk < 4; kk++) {
                const int q = kk >> 1, ix = (kk & 1) * 2;
                unsigned b0h = kh[q][ix], b1h = kh[q][ix + 1];
                unsigned b0l = kl[q][ix], b1l = kl[q][ix + 1];
                mma16816(sc_[ni], qh[kk], b0h, b1h);
                mma16816(sc_[ni], qh[kk], b0l, b1l);
                mma16816(sc_[ni], ql[kk], b0h, b1h);
            }
        }

        const float scale = 0.125f;
        const int rA = qt * 128 + w * 16 + g;
        const int rB = rA + 8;
        if (kt * 64 + 63 > qt * 128 + w * 16) {
#pragma unroll
            for (int ni = 0; ni < 8; ni++) {
                int c0 = kt * 64 + ni * 8 + tg * 2;
                sc_[ni][0] = (c0     > rA) ? NEG : sc_[ni][0] * scale;
                sc_[ni][1] = (c0 + 1 > rA) ? NEG : sc_[ni][1] * scale;
                sc_[ni][2] = (c0     > rB) ? NEG : sc_[ni][2] * scale;
                sc_[ni][3] = (c0 + 1 > rB) ? NEG : sc_[ni][3] * scale;
            }
        } else {
#pragma unroll
            for (int ni = 0; ni < 8; ni++)
#pragma unroll
                for (int j = 0; j < 4; j++) sc_[ni][j] *= scale;
        }

        float mx0 = NEG, mx1 = NEG;
#pragma unroll
        for (int ni = 0; ni < 8; ni++) {
            mx0 = fmaxf(mx0, fmaxf(sc_[ni][0], sc_[ni][1]));
            mx1 = fmaxf(mx1, fmaxf(sc_[ni][2], sc_[ni][3]));
        }
        mx0 = fmaxf(mx0, __shfl_xor_sync(0xffffffffu, mx0, 1));
        mx0 = fmaxf(mx0, __shfl_xor_sync(0xffffffffu, mx0, 2));
        mx1 = fmaxf(mx1, __shfl_xor_sync(0xffffffffu, mx1, 1));
        mx1 = fmaxf(mx1, __shfl_xor_sync(0xffffffffu, mx1, 2));

        float nm0 = fmaxf(m0v, mx0), nm1 = fmaxf(m1v, mx1);
        float corr0 = __expf(m0v - nm0), corr1 = __expf(m1v - nm1);

        float sum0 = 0.f, sum1 = 0.f;
#pragma unroll
        for (int ni = 0; ni < 8; ni++) {
            sc_[ni][0] = __expf(sc_[ni][0] - nm0);
            sc_[ni][1] = __expf(sc_[ni][1] - nm0);
            sc_[ni][2] = __expf(sc_[ni][2] - nm1);
            sc_[ni][3] = __expf(sc_[ni][3] - nm1);
            sum0 += sc_[ni][0] + sc_[ni][1];
            sum1 += sc_[ni][2] + sc_[ni][3];
        }
        sum0 += __shfl_xor_sync(0xffffffffu, sum0, 1);
        sum0 += __shfl_xor_sync(0xffffffffu, sum0, 2);
        sum1 += __shfl_xor_sync(0xffffffffu, sum1, 1);
        sum1 += __shfl_xor_sync(0xffffffffu, sum1, 2);

        l0v = l0v * corr0 + sum0;
        l1v = l1v * corr1 + sum1;
        m0v = nm0; m1v = nm1;

#pragma unroll
        for (int ni = 0; ni < 8; ni++) {
            o[ni][0] *= corr0; o[ni][1] *= corr0;
            o[ni][2] *= corr1; o[ni][3] *= corr1;
        }

#pragma unroll
        for (int j = 0; j < 4; j++) {
            unsigned ah[4], al[4];
            {
                __nv_bfloat16 h0, l0, h1, l1;
                splitf(sc_[2 * j][0], h0, l0); splitf(sc_[2 * j][1], h1, l1);
                ah[0] = packh(h0, h1); al[0] = packh(l0, l1);
                splitf(sc_[2 * j][2], h0, l0); splitf(sc_[2 * j][3], h1, l1);
                ah[1] = packh(h0, h1); al[1] = packh(l0, l1);
                splitf(sc_[2 * j + 1][0], h0, l0); splitf(sc_[2 * j + 1][1], h1, l1);
                ah[2] = packh(h0, h1); al[2] = packh(l0, l1);
                splitf(sc_[2 * j + 1][2], h0, l0); splitf(sc_[2 * j + 1][3], h1, l1);
                ah[3] = packh(h0, h1); al[3] = packh(l0, l1);
            }
            unsigned vh[4][4], vl[4][4];
#pragma unroll
            for (int p = 0; p < 4; p++) {
                unsigned off = sb + 2 * A_ARR + j * 16 * ALD + p * 16 + vbase;
                ldsm_x4t(vh[p], smb + off * 2);
                ldsm_x4t(vl[p], smb + (off + A_ARR) * 2);
            }
#pragma unroll
            for (int ni = 0; ni < 8; ni++) {
                const int p = ni >> 1, ix = (ni & 1) * 2;
                unsigned b0h = vh[p][ix], b1h = vh[p][ix + 1];
                unsigned b0l = vl[p][ix], b1l = vl[p][ix + 1];
                mma16816(o[ni], ah, b0h, b1h);
                mma16816(o[ni], ah, b0l, b1l);
                mma16816(o[ni], al, b0h, b1h);
            }
        }
    }

    float inv0 = 1.f / l0v, inv1 = 1.f / l1v;
    int bb = bh >> 4, hh = bh & 15;
    int q0 = qt * 128 + w * 16 + g;
#pragma unroll
    for (int ni = 0; ni < 8; ni++) {
        int d = ni * 8 + tg * 2;
        size_t i0 = ((size_t)(bb * S_ + q0)) * D_ + hh * 64 + d;
        size_t i1 = ((size_t)(bb * S_ + q0 + 8)) * D_ + hh * 64 + d;
        __nv_bfloat16 h0, l0, h1, l1;
        splitf(o[ni][0] * inv0, h0, l0); splitf(o[ni][1] * inv0, h1, l1);
        *(unsigned*)&Ch[i0] = packh(h0, h1);
        *(unsigned*)&Cl[i0] = packh(l0, l1);
        splitf(o[ni][2] * inv1, h0, l0); splitf(o[ni][3] * inv1, h1, l1);
        *(unsigned*)&Ch[i1] = packh(h0, h1);
        *(unsigned*)&Cl[i1] = packh(l0, l1);
    }
}

// ============================================================================
// Launch
// ============================================================================
extern "C" void kernel_launch(void* const* d_in, const int* in_sizes, int n_in,
                              void* d_out, int out_size)
{
    const float* q  = (const float*)d_in[0];
    const float* k  = (const float*)d_in[1];
    const float* v  = (const float*)d_in[2];
    const float* wq = (const float*)d_in[4];
    const float* bq = (const float*)d_in[5];
    const float* wk = (const float*)d_in[6];
    const float* bk = (const float*)d_in[7];
    const float* wv = (const float*)d_in[8];
    const float* bv = (const float*)d_in[9];
    const float* wo = (const float*)d_in[10];
    const float* bo = (const float*)d_in[11];
    float* out = (float*)d_out;

    __nv_bfloat16 *gxh, *gxl, *gwh, *gwl, *gh, *gl, *gch, *gcl;
    cudaGetSymbolAddress((void**)&gxh, g_xh);
    cudaGetSymbolAddress((void**)&gxl, g_xl);
    cudaGetSymbolAddress((void**)&gwh, g_wh);
    cudaGetSymbolAddress((void**)&gwl, g_wl);
    cudaGetSymbolAddress((void**)&gh,  g_h);
    cudaGetSymbolAddress((void**)&gl,  g_l);
    cudaGetSymbolAddress((void**)&gch, g_ch);
    cudaGetSymbolAddress((void**)&gcl, g_cl);

    cudaFuncSetAttribute(gemm_kernel<0>,
                         cudaFuncAttributeMaxDynamicSharedMemorySize, GEMM_SMEM);
    cudaFuncSetAttribute(gemm_kernel<1>,
                         cudaFuncAttributeMaxDynamicSharedMemorySize, GEMM_SMEM);
    cudaFuncSetAttribute(attn_kernel,
                         cudaFuncAttributeMaxDynamicSharedMemorySize, ATTN_SMEM);

    // 1) split inputs + weights to bf16 hi/lo
    convert_kernel<<<16384, 256>>>(q, k, v, wq, wk, wv, wo);

    // 2) QKV projections (persistent: 296 CTAs over 768 tiles)
    gemm_kernel<0><<<GEMM_GRID0, 256, GEMM_SMEM>>>(
        gxh, gxl, gwh, gwl, bq, bk, bv, gh, gl, nullptr);

    // 3) attention
    attn_kernel<<<dim3(S_ / 128, B_ * H_), 256, ATTN_SMEM>>>(gh, gl, gch, gcl);

    // 4) output projection (256 tiles, single wave)
    gemm_kernel<1><<<256, 256, GEMM_SMEM>>>(
        gch, gcl, gwh + 3 * WSZ, gwl + 3 * WSZ, bo, bo, bo, nullptr, nullptr, out);
}

// round 10
// speedup vs baseline: 1.0261x; 1.0261x over previous
#include <cuda_runtime.h>
#include <cuda_bf16.h>
#include <cstdint>

#define DINLINE __device__ __forceinline__

constexpr int B_  = 2;
constexpr int S_  = 2048;
constexpr int D_  = 1024;
constexpr int H_  = 16;
constexpr int DK_ = 64;

constexpr size_t NQKV = (size_t)B_ * H_ * S_ * DK_;   // 4M elems
constexpr size_t XSZ  = (size_t)4096 * 1024;          // 4M
constexpr size_t WSZ  = (size_t)1024 * 1024;          // 1M

// ---------------- global scratch ----------------
__device__ __nv_bfloat16 g_xh[3 * XSZ], g_xl[3 * XSZ];     // q,k,v inputs split
__device__ __nv_bfloat16 g_wh[4 * WSZ], g_wl[4 * WSZ];     // wq,wk,wv,wo split
__device__ __nv_bfloat16 g_h[3 * NQKV], g_l[3 * NQKV];     // Q,K,V proj [B,H,S,DK]
__device__ __nv_bfloat16 g_ch[XSZ], g_cl[XSZ];             // attn context split

// ---------------- helpers ----------------
DINLINE unsigned packh(__nv_bfloat16 a, __nv_bfloat16 b) {
    __nv_bfloat162 v; v.x = a; v.y = b;
    return *reinterpret_cast<unsigned*>(&v);
}
DINLINE void splitf(float x, __nv_bfloat16& h, __nv_bfloat16& l) {
    h = __float2bfloat16(x);
    l = __float2bfloat16(x - __bfloat162float(h));
}
DINLINE void mma16816(float* c, const unsigned* a, unsigned b0, unsigned b1) {
    asm volatile(
        "mma.sync.aligned.m16n8k16.row.col.f32.bf16.bf16.f32 "
        "{%0,%1,%2,%3},{%4,%5,%6,%7},{%8,%9},{%0,%1,%2,%3};\n"
        : "+f"(c[0]), "+f"(c[1]), "+f"(c[2]), "+f"(c[3])
        : "r"(a[0]), "r"(a[1]), "r"(a[2]), "r"(a[3]), "r"(b0), "r"(b1));
}
DINLINE unsigned smem_u32(const void* p) {
    unsigned a;
    asm("{.reg .u64 t; cvta.to.shared.u64 t, %1; cvt.u32.u64 %0, t;}" : "=r"(a) : "l"(p));
    return a;
}
DINLINE void ldsm_x4(unsigned* r, unsigned addr) {
    asm volatile("ldmatrix.sync.aligned.m8n8.x4.shared.b16 {%0,%1,%2,%3}, [%4];"
                 : "=r"(r[0]), "=r"(r[1]), "=r"(r[2]), "=r"(r[3]) : "r"(addr));
}
DINLINE void ldsm_x4t(unsigned* r, unsigned addr) {
    asm volatile("ldmatrix.sync.aligned.m8n8.x4.trans.shared.b16 {%0,%1,%2,%3}, [%4];"
                 : "=r"(r[0]), "=r"(r[1]), "=r"(r[2]), "=r"(r[3]) : "r"(addr));
}

#define CP_ASYNC16(dst, src) \
    asm volatile("cp.async.cg.shared.global [%0], [%1], 16;\n" :: "r"(dst), "l"(src))
#define CP_COMMIT()  asm volatile("cp.async.commit_group;\n")
#define CP_WAIT0()   asm volatile("cp.async.wait_group 0;\n")
#define CP_WAIT1()   asm volatile("cp.async.wait_group 1;\n")

// ============================================================================
// convert: f32 inputs/weights -> bf16 hi/lo global buffers
// ============================================================================
__global__ void __launch_bounds__(256) convert_kernel(
    const float* __restrict__ q, const float* __restrict__ k, const float* __restrict__ v,
    const float* __restrict__ wq, const float* __restrict__ wk,
    const float* __restrict__ wv, const float* __restrict__ wo)
{
    size_t i = ((size_t)blockIdx.x * 256 + threadIdx.x) * 4;
    const float* src;
    __nv_bfloat16 *dh, *dl;
    size_t off;
    if (i < (size_t)3 * XSZ) {
        int z = (int)(i / XSZ);
        off = i - (size_t)z * XSZ;
        src = (z == 0) ? q : (z == 1) ? k : v;
        dh = g_xh + (size_t)z * XSZ; dl = g_xl + (size_t)z * XSZ;
    } else {
        size_t j = i - (size_t)3 * XSZ;
        int z = (int)(j / WSZ);
        off = j - (size_t)z * WSZ;
        src = (z == 0) ? wq : (z == 1) ? wk : (z == 2) ? wv : wo;
        dh = g_wh + (size_t)z * WSZ; dl = g_wl + (size_t)z * WSZ;
    }
    float4 val = *(const float4*)(src + off);
    __nv_bfloat16 h0, l0, h1, l1, h2, l2, h3, l3;
    splitf(val.x, h0, l0); splitf(val.y, h1, l1);
    splitf(val.z, h2, l2); splitf(val.w, h3, l3);
    uint2 uh = { packh(h0, h1), packh(h2, h3) };
    uint2 ul = { packh(l0, l1), packh(l2, l3) };
    *(uint2*)(dh + off) = uh;
    *(uint2*)(dl + off) = ul;
}

// ============================================================================
// GEMM: Y[4096,1024] = X @ W^T + b, pre-split bf16 hi/lo, 3-term.
// Tile 128x128, 256 threads (8 warps, warptile 32x64), BK=32.
// 3-stage cp.async pipeline, ONE __syncthreads per K-iteration, R8 body order
// (issue_stage immediately after barrier — ptxas schedules this best).
// XOR-swizzled smem chunks (conflict-free, no pad). Stage=32KB, 3 stages=96KB,
// 2 CTAs/SM.
// MODE 0: PERSISTENT over 768 tiles (grid 296); hi/lo bf16 out [B,H,S,DK].
// MODE 1: direct blockIdx mapping (grid 8x32), f32 out — byte-identical to R8.
// ============================================================================
constexpr int G_ARR_B   = 128 * 64;            // 8192 bytes per array
constexpr int G_STAGE_B = 4 * G_ARR_B;         // 32768 bytes per stage
constexpr int GEMM_SMEM = 3 * G_STAGE_B;       // 98304 bytes
constexpr int GEMM_GRID0 = 296;                // 148 SMs x 2 CTAs

template<int MODE>
__global__ void __launch_bounds__(256, 2) gemm_kernel(
    const __nv_bfloat16* __restrict__ Ahg, const __nv_bfloat16* __restrict__ Alg,
    const __nv_bfloat16* __restrict__ Whg, const __nv_bfloat16* __restrict__ Wlg,
    const float* __restrict__ b0p, const float* __restrict__ b1p, const float* __restrict__ b2p,
    __nv_bfloat16* __restrict__ Yh, __nv_bfloat16* __restrict__ Yl,
    float* __restrict__ Yf)
{
    extern __shared__ __nv_bfloat16 gsm[];
    const unsigned smb = smem_u32(gsm);

    const int t    = threadIdx.x;
    const int w    = t >> 5;
    const int lane = t & 31;
    const int g    = lane >> 2;
    const int tg   = lane & 3;
    const int lm   = lane >> 3;   // ldmatrix matrix id (0..3)
    const int lr   = lane & 7;    // ldmatrix row-in-matrix
    const int wm   = w >> 1;      // 0..3
    const int wn   = w & 1;       // 0..1

    // tile-independent ldmatrix per-lane bases
    unsigned aoff[2], axor[2], boff[4], bxor[4];
    const unsigned aC = (unsigned)(lm >> 1);
    const unsigned bC = (unsigned)(lm & 1);
#pragma unroll
    for (int mi = 0; mi < 2; mi++) {
        int r = wm * 32 + mi * 16 + ((lm & 1) << 3) + lr;
        aoff[mi] = (unsigned)r * 64u;
        axor[mi] = (unsigned)((r >> 1) & 3);
    }
#pragma unroll
    for (int p = 0; p < 4; p++) {
        int r = wn * 64 + p * 16 + ((lm >> 1) << 3) + lr;
        boff[p] = (unsigned)r * 64u;
        bxor[p] = (unsigned)((r >> 1) & 3);
    }

    auto run_tile = [&](int z, int m0, int n0) {
        const __nv_bfloat16* Ah = Ahg + (size_t)z * XSZ;
        const __nv_bfloat16* Al = Alg + (size_t)z * XSZ;
        const __nv_bfloat16* Bh = Whg + (size_t)z * WSZ;
        const __nv_bfloat16* Bl = Wlg + (size_t)z * WSZ;
        const float* bias = (z == 0) ? b0p : (z == 1) ? b1p : b2p;

        float acc[2][8][4];
#pragma unroll
        for (int mi = 0; mi < 2; mi++)
#pragma unroll
            for (int ni = 0; ni < 8; ni++)
#pragma unroll
                for (int j = 0; j < 4; j++) acc[mi][ni][j] = 0.f;

        auto issue_stage = [&](int kt, int stg) {
            const unsigned base = (unsigned)(stg * G_STAGE_B);
#pragma unroll
            for (int i = 0; i < 8; i++) {
                int id = t + i * 256;
                int a_ = id >> 9;                 // array 0..3
                int cid = id & 511;
                int row = cid >> 2, c = cid & 3;
                const __nv_bfloat16* gp =
                    (a_ == 0) ? Ah : (a_ == 1) ? Al : (a_ == 2) ? Bh : Bl;
                const int r0 = (a_ < 2) ? m0 : n0;
                unsigned dst = smb + base + (unsigned)a_ * G_ARR_B
                             + (unsigned)row * 64u
                             + ((unsigned)(c ^ ((row >> 1) & 3)) << 4);
                CP_ASYNC16(dst, gp + (size_t)(r0 + row) * 1024 + (size_t)kt * 32 + c * 8);
            }
            CP_COMMIT();
        };

        issue_stage(0, 0);
        issue_stage(1, 1);

        for (int kt = 0; kt < 32; kt++) {
            if (kt < 31) CP_WAIT1(); else CP_WAIT0();
            __syncthreads();          // tile kt ready AND compute of kt-1 done

            if (kt + 2 < 32) issue_stage(kt + 2, (kt + 2) % 3);

            const unsigned sb = smb + (unsigned)((kt % 3) * G_STAGE_B);
#pragma unroll
            for (int kk2 = 0; kk2 < 2; kk2++) {
                unsigned ah[2][4], al[2][4], bh[4][4], bl[4][4];
#pragma unroll
                for (int mi = 0; mi < 2; mi++) {
                    unsigned cidx = (((unsigned)(2 * kk2) + aC) ^ axor[mi]) << 4;
                    ldsm_x4(ah[mi], sb + aoff[mi] + cidx);
                    ldsm_x4(al[mi], sb + G_ARR_B + aoff[mi] + cidx);
                }
#pragma unroll
                for (int p = 0; p < 4; p++) {
                    unsigned cidx = (((unsigned)(2 * kk2) + bC) ^ bxor[p]) << 4;
                    ldsm_x4(bh[p], sb + 2 * G_ARR_B + boff[p] + cidx);
                    ldsm_x4(bl[p], sb + 3 * G_ARR_B + boff[p] + cidx);
                }
#pragma unroll
                for (int ni = 0; ni < 8; ni++) {
                    const int p = ni >> 1, ix = (ni & 1) * 2;
                    unsigned b0h = bh[p][ix], b1h = bh[p][ix + 1];
                    unsigned b0l = bl[p][ix], b1l = bl[p][ix + 1];
#pragma unroll
                    for (int mi = 0; mi < 2; mi++) {
                        mma16816(acc[mi][ni], ah[mi], b0h, b1h);
                        mma16816(acc[mi][ni], ah[mi], b0l, b1l);
                        mma16816(acc[mi][ni], al[mi], b0h, b1h);
                    }
                }
            }
        }

        // ---- epilogue ----
        const size_t zoff = (size_t)z * NQKV;
#pragma unroll
        for (int mi = 0; mi < 2; mi++) {
#pragma unroll
            for (int ni = 0; ni < 8; ni++) {
                int r = m0 + wm * 32 + mi * 16 + g;
                int c = n0 + wn * 64 + ni * 8 + tg * 2;
                float b0 = bias[c], b1 = bias[c + 1];
                float v00 = acc[mi][ni][0] + b0;
                float v01 = acc[mi][ni][1] + b1;
                float v10 = acc[mi][ni][2] + b0;
                float v11 = acc[mi][ni][3] + b1;
                if (MODE == 0) {
                    int bb = r >> 11, ss = r & 2047;
                    int hh = c >> 6, d = c & 63;
                    size_t i0 = zoff + ((size_t)(bb * H_ + hh) * S_ + ss) * DK_ + d;
                    size_t i1 = zoff + ((size_t)(bb * H_ + hh) * S_ + (ss + 8)) * DK_ + d;
                    __nv_bfloat16 h0, l0, h1, l1;
                    splitf(v00, h0, l0); splitf(v01, h1, l1);
                    *(unsigned*)&Yh[i0] = packh(h0, h1);
                    *(unsigned*)&Yl[i0] = packh(l0, l1);
                    splitf(v10, h0, l0); splitf(v11, h1, l1);
                    *(unsigned*)&Yh[i1] = packh(h0, h1);
                    *(unsigned*)&Yl[i1] = packh(l0, l1);
                } else {
                    Yf[(size_t)r * 1024 + c]           = v00;
                    Yf[(size_t)r * 1024 + c + 1]       = v01;
                    Yf[(size_t)(r + 8) * 1024 + c]     = v10;
                    Yf[(size_t)(r + 8) * 1024 + c + 1] = v11;
                }
            }
        }
    };

    if (MODE == 0) {
        for (int tid = blockIdx.x; tid < 768; tid += gridDim.x) {
            const int z   = tid >> 8;
            const int rem = tid & 255;
            run_tile(z, (rem >> 3) * 128, (rem & 7) * 128);
        }
    } else {
        run_tile(0, blockIdx.y * 128, blockIdx.x * 128);
    }
}

// ============================================================================
// Flash attention (causal), DK=64, Q-tile 128 (8 warps x 16 rows), KV-tile 64.
// (byte-identical to R8 passing version)
// ============================================================================
constexpr int ALD = 72;
constexpr int A_ARR = 64 * ALD;         // 4608 elems per array
constexpr int STAGE = 4 * A_ARR;        // Kh,Kl,Vh,Vl
constexpr int ATTN_SMEM = 2 * STAGE * 2;

__global__ void __launch_bounds__(256, 1) attn_kernel(
    const __nv_bfloat16* __restrict__ Gh, const __nv_bfloat16* __restrict__ Gl,
    __nv_bfloat16* __restrict__ Ch, __nv_bfloat16* __restrict__ Cl)
{
    extern __shared__ __nv_bfloat16 sm[];

    const int qt   = (int)gridDim.x - 1 - (int)blockIdx.x;  // heavy first
    const int bh   = blockIdx.y;
    const int t    = threadIdx.x;
    const int w    = t >> 5;
    const int lane = t & 31;
    const int g    = lane >> 2;
    const int tg   = lane & 3;
    const int lm   = lane >> 3;
    const int lr   = lane & 7;

    const size_t hb = (size_t)bh * S_ * DK_;
    const __nv_bfloat16* Qhb = Gh + hb;
    const __nv_bfloat16* Qlb = Gl + hb;
    const __nv_bfloat16* Khb = Gh + NQKV + hb;
    const __nv_bfloat16* Klb = Gl + NQKV + hb;
    const __nv_bfloat16* Vhb = Gh + 2 * NQKV + hb;
    const __nv_bfloat16* Vlb = Gl + 2 * NQKV + hb;

    const unsigned smb = smem_u32(sm);
    const float NEG = -1e30f;

    const int kbase = lr * ALD + (lm << 3);
    const int vbase = (((lm & 1) << 3) + lr) * ALD + ((lm >> 1) << 3);

    unsigned qh[4][4], ql[4][4];
    {
        size_t r0 = (size_t)(qt * 128 + w * 16 + g) * DK_;
        size_t r1 = r0 + 8 * DK_;
#pragma unroll
        for (int kk = 0; kk < 4; kk++) {
            int c = kk * 16 + tg * 2;
            qh[kk][0] = *(const unsigned*)&Qhb[r0 + c];
            qh[kk][1] = *(const unsigned*)&Qhb[r1 + c];
            qh[kk][2] = *(const unsigned*)&Qhb[r0 + c + 8];
            qh[kk][3] = *(const unsigned*)&Qhb[r1 + c + 8];
            ql[kk][0] = *(const unsigned*)&Qlb[r0 + c];
            ql[kk][1] = *(const unsigned*)&Qlb[r1 + c];
            ql[kk][2] = *(const unsigned*)&Qlb[r0 + c + 8];
            ql[kk][3] = *(const unsigned*)&Qlb[r1 + c + 8];
        }
    }

    auto issue_tile = [&](int kt, int stg) {
#pragma unroll
        for (int i = 0; i < 8; i++) {
            int id = t + i * 256;
            int a_ = id >> 9;
            int cid = id & 511;
            int row = cid >> 3, seg = cid & 7;
            const __nv_bfloat16* gp =
                (a_ == 0) ? Khb : (a_ == 1) ? Klb : (a_ == 2) ? Vhb : Vlb;
            unsigned dst = smb + (unsigned)(stg * STAGE + a_ * A_ARR + row * ALD + seg * 8) * 2;
            CP_ASYNC16(dst, gp + (size_t)(kt * 64 + row) * DK_ + seg * 8);
        }
        CP_COMMIT();
    };

    float m0v = NEG, m1v = NEG, l0v = 0.f, l1v = 0.f;
    float o[8][4];
#pragma unroll
    for (int ni = 0; ni < 8; ni++)
#pragma unroll
        for (int j = 0; j < 4; j++) o[ni][j] = 0.f;

    const int ktmax = 2 * qt + 2;
    issue_tile(0, 0);

    for (int kt = 0; kt < ktmax; kt++) {
        const int s = kt & 1;
        CP_WAIT0();
        __syncthreads();

        if (kt + 1 < ktmax) issue_tile(kt + 1, s ^ 1);

        const unsigned sb = (unsigned)(s * STAGE);

        float sc_[8][4];
#pragma unroll
        for (int ni = 0; ni < 8; ni++) {
#pragma unroll
            for (int j = 0; j < 4; j++) sc_[ni][j] = 0.f;
            unsigned kh[2][4], kl[2][4];
#pragma unroll
            for (int q = 0; q < 2; q++) {
                unsigned off = sb + ni * 8 * ALD + q * 32 + kbase;
                ldsm_x4(kh[q], smb + off * 2);
                ldsm_x4(kl[q], smb + (off + A_ARR) * 2);
            }
#pragma unroll
            for (int kk = 0; kk < 4; kk++) {
                const int q = kk >> 1, ix = (kk & 1) * 2;
                unsigned b0h = kh[q][ix], b1h = kh[q][ix + 1];
                unsigned b0l = kl[q][ix], b1l = kl[q][ix + 1];
                mma16816(sc_[ni], qh[kk], b0h, b1h);
                mma16816(sc_[ni], qh[kk], b0l, b1l);
                mma16816(sc_[ni], ql[kk], b0h, b1h);
            }
        }

        const float scale = 0.125f;
        const int rA = qt * 128 + w * 16 + g;
        const int rB = rA + 8;
        if (kt * 64 + 63 > qt * 128 + w * 16) {
#pragma unroll
            for (int ni = 0; ni < 8; ni++) {
                int c0 = kt * 64 + ni * 8 + tg * 2;
                sc_[ni][0] = (c0     > rA) ? NEG : sc_[ni][0] * scale;
                sc_[ni][1] = (c0 + 1 > rA) ? NEG : sc_[ni][1] * scale;
                sc_[ni][2] = (c0     > rB) ? NEG : sc_[ni][2] * scale;
                sc_[ni][3] = (c0 + 1 > rB) ? NEG : sc_[ni][3] * scale;
            }
        } else {
#pragma unroll
            for (int ni = 0; ni < 8; ni++)
#pragma unroll
                for (int j = 0; j < 4; j++) sc_[ni][j] *= scale;
        }

        float mx0 = NEG, mx1 = NEG;
#pragma unroll
        for (int ni = 0; ni < 8; ni++) {
            mx0 = fmaxf(mx0, fmaxf(sc_[ni][0], sc_[ni][1]));
            mx1 = fmaxf(mx1, fmaxf(sc_[ni][2], sc_[ni][3]));
        }
        mx0 = fmaxf(mx0, __shfl_xor_sync(0xffffffffu, mx0, 1));
        mx0 = fmaxf(mx0, __shfl_xor_sync(0xffffffffu, mx0, 2));
        mx1 = fmaxf(mx1, __shfl_xor_sync(0xffffffffu, mx1, 1));
        mx1 = fmaxf(mx1, __shfl_xor_sync(0xffffffffu, mx1, 2));

        float nm0 = fmaxf(m0v, mx0), nm1 = fmaxf(m1v, mx1);
        float corr0 = __expf(m0v - nm0), corr1 = __expf(m1v - nm1);

        float sum0 = 0.f, sum1 = 0.f;
#pragma unroll
        for (int ni = 0; ni < 8; ni++) {
            sc_[ni][0] = __expf(sc_[ni][0] - nm0);
            sc_[ni][1] = __expf(sc_[ni][1] - nm0);
            sc_[ni][2] = __expf(sc_[ni][2] - nm1);
            sc_[ni][3] = __expf(sc_[ni][3] - nm1);
            sum0 += sc_[ni][0] + sc_[ni][1];
            sum1 += sc_[ni][2] + sc_[ni][3];
        }
        sum0 += __shfl_xor_sync(0xffffffffu, sum0, 1);
        sum0 += __shfl_xor_sync(0xffffffffu, sum0, 2);
        sum1 += __shfl_xor_sync(0xffffffffu, sum1, 1);
        sum1 += __shfl_xor_sync(0xffffffffu, sum1, 2);

        l0v = l0v * corr0 + sum0;
        l1v = l1v * corr1 + sum1;
        m0v = nm0; m1v = nm1;

#pragma unroll
        for (int ni = 0; ni < 8; ni++) {
            o[ni][0] *= corr0; o[ni][1] *= corr0;
            o[ni][2] *= corr1; o[ni][3] *= corr1;
        }

#pragma unroll
        for (int j = 0; j < 4; j++) {
            unsigned ah[4], al[4];
            {
                __nv_bfloat16 h0, l0, h1, l1;
                splitf(sc_[2 * j][0], h0, l0); splitf(sc_[2 * j][1], h1, l1);
                ah[0] = packh(h0, h1); al[0] = packh(l0, l1);
                splitf(sc_[2 * j][2], h0, l0); splitf(sc_[2 * j][3], h1, l1);
                ah[1] = packh(h0, h1); al[1] = packh(l0, l1);
                splitf(sc_[2 * j + 1][0], h0, l0); splitf(sc_[2 * j + 1][1], h1, l1);
                ah[2] = packh(h0, h1); al[2] = packh(l0, l1);
                splitf(sc_[2 * j + 1][2], h0, l0); splitf(sc_[2 * j + 1][3], h1, l1);
                ah[3] = packh(h0, h1); al[3] = packh(l0, l1);
            }
            unsigned vh[4][4], vl[4][4];
#pragma unroll
            for (int p = 0; p < 4; p++) {
                unsigned off = sb + 2 * A_ARR + j * 16 * ALD + p * 16 + vbase;
                ldsm_x4t(vh[p], smb + off * 2);
                ldsm_x4t(vl[p], smb + (off + A_ARR) * 2);
            }
#pragma unroll
            for (int ni = 0; ni < 8; ni++) {
                const int p = ni >> 1, ix = (ni & 1) * 2;
                unsigned b0h = vh[p][ix], b1h = vh[p][ix + 1];
                unsigned b0l = vl[p][ix], b1l = vl[p][ix + 1];
                mma16816(o[ni], ah, b0h, b1h);
                mma16816(o[ni], ah, b0l, b1l);
                mma16816(o[ni], al, b0h, b1h);
            }
        }
    }

    float inv0 = 1.f / l0v, inv1 = 1.f / l1v;
    int bb = bh >> 4, hh = bh & 15;
    int q0 = qt * 128 + w * 16 + g;
#pragma unroll
    for (int ni = 0; ni < 8; ni++) {
        int d = ni * 8 + tg * 2;
        size_t i0 = ((size_t)(bb * S_ + q0)) * D_ + hh * 64 + d;
        size_t i1 = ((size_t)(bb * S_ + q0 + 8)) * D_ + hh * 64 + d;
        __nv_bfloat16 h0, l0, h1, l1;
        splitf(o[ni][0] * inv0, h0, l0); splitf(o[ni][1] * inv0, h1, l1);
        *(unsigned*)&Ch[i0] = packh(h0, h1);
        *(unsigned*)&Cl[i0] = packh(l0, l1);
        splitf(o[ni][2] * inv1, h0, l0); splitf(o[ni][3] * inv1, h1, l1);
        *(unsigned*)&Ch[i1] = packh(h0, h1);
        *(unsigned*)&Cl[i1] = packh(l0, l1);
    }
}

// ============================================================================
// Launch
// ============================================================================
extern "C" void kernel_launch(void* const* d_in, const int* in_sizes, int n_in,
                              void* d_out, int out_size)
{
    const float* q  = (const float*)d_in[0];
    const float* k  = (const float*)d_in[1];
    const float* v  = (const float*)d_in[2];
    const float* wq = (const float*)d_in[4];
    const float* bq = (const float*)d_in[5];
    const float* wk = (const float*)d_in[6];
    const float* bk = (const float*)d_in[7];
    const float* wv = (const float*)d_in[8];
    const float* bv = (const float*)d_in[9];
    const float* wo = (const float*)d_in[10];
    const float* bo = (const float*)d_in[11];
    float* out = (float*)d_out;

    __nv_bfloat16 *gxh, *gxl, *gwh, *gwl, *gh, *gl, *gch, *gcl;
    cudaGetSymbolAddress((void**)&gxh, g_xh);
    cudaGetSymbolAddress((void**)&gxl, g_xl);
    cudaGetSymbolAddress((void**)&gwh, g_wh);
    cudaGetSymbolAddress((void**)&gwl, g_wl);
    cudaGetSymbolAddress((void**)&gh,  g_h);
    cudaGetSymbolAddress((void**)&gl,  g_l);
    cudaGetSymbolAddress((void**)&gch, g_ch);
    cudaGetSymbolAddress((void**)&gcl, g_cl);

    cudaFuncSetAttribute(gemm_kernel<0>,
                         cudaFuncAttributeMaxDynamicSharedMemorySize, GEMM_SMEM);
    cudaFuncSetAttribute(gemm_kernel<1>,
                         cudaFuncAttributeMaxDynamicSharedMemorySize, GEMM_SMEM);
    cudaFuncSetAttribute(attn_kernel,
                         cudaFuncAttributeMaxDynamicSharedMemorySize, ATTN_SMEM);

    // 1) split inputs + weights to bf16 hi/lo
    convert_kernel<<<16384, 256>>>(q, k, v, wq, wk, wv, wo);

    // 2) QKV projections (persistent: 296 CTAs over 768 tiles, R8 body)
    gemm_kernel<0><<<GEMM_GRID0, 256, GEMM_SMEM>>>(
        gxh, gxl, gwh, gwl, bq, bk, bv, gh, gl, nullptr);

    // 3) attention
    attn_kernel<<<dim3(S_ / 128, B_ * H_), 256, ATTN_SMEM>>>(gh, gl, gch, gcl);

    // 4) output projection (R8 mapping: grid 8x32, no loop)
    gemm_kernel<1><<<dim3(8, 32, 1), 256, GEMM_SMEM>>>(
        gch, gcl, gwh + 3 * WSZ, gwl + 3 * WSZ, bo, bo, bo, nullptr, nullptr, out);
}

// round 12
// speedup vs baseline: 1.0459x; 1.0193x over previous
#include <cuda_runtime.h>
#include <cuda_bf16.h>
#include <cstdint>

#define DINLINE __device__ __forceinline__

constexpr int B_  = 2;
constexpr int S_  = 2048;
constexpr int D_  = 1024;
constexpr int H_  = 16;
constexpr int DK_ = 64;

constexpr size_t NQKV = (size_t)B_ * H_ * S_ * DK_;   // 4M elems
constexpr size_t XSZ  = (size_t)4096 * 1024;          // 4M
constexpr size_t WSZ  = (size_t)1024 * 1024;          // 1M

// ---------------- global scratch ----------------
__device__ __nv_bfloat16 g_xh[3 * XSZ], g_xl[3 * XSZ];     // q,k,v inputs split
__device__ __nv_bfloat16 g_wh[4 * WSZ], g_wl[4 * WSZ];     // wq,wk,wv,wo split
__device__ __nv_bfloat16 g_h[3 * NQKV], g_l[3 * NQKV];     // Q,K,V proj [B,H,S,DK]
__device__ __nv_bfloat16 g_ch[XSZ], g_cl[XSZ];             // attn context split

// ---------------- helpers ----------------
DINLINE unsigned packh(__nv_bfloat16 a, __nv_bfloat16 b) {
    __nv_bfloat162 v; v.x = a; v.y = b;
    return *reinterpret_cast<unsigned*>(&v);
}
DINLINE void splitf(float x, __nv_bfloat16& h, __nv_bfloat16& l) {
    h = __float2bfloat16(x);
    l = __float2bfloat16(x - __bfloat162float(h));
}
DINLINE void mma16816(float* c, const unsigned* a, unsigned b0, unsigned b1) {
    asm volatile(
        "mma.sync.aligned.m16n8k16.row.col.f32.bf16.bf16.f32 "
        "{%0,%1,%2,%3},{%4,%5,%6,%7},{%8,%9},{%0,%1,%2,%3};\n"
        : "+f"(c[0]), "+f"(c[1]), "+f"(c[2]), "+f"(c[3])
        : "r"(a[0]), "r"(a[1]), "r"(a[2]), "r"(a[3]), "r"(b0), "r"(b1));
}
DINLINE unsigned smem_u32(const void* p) {
    unsigned a;
    asm("{.reg .u64 t; cvta.to.shared.u64 t, %1; cvt.u32.u64 %0, t;}" : "=r"(a) : "l"(p));
    return a;
}
DINLINE void ldsm_x4(unsigned* r, unsigned addr) {
    asm volatile("ldmatrix.sync.aligned.m8n8.x4.shared.b16 {%0,%1,%2,%3}, [%4];"
                 : "=r"(r[0]), "=r"(r[1]), "=r"(r[2]), "=r"(r[3]) : "r"(addr));
}
DINLINE void ldsm_x4t(unsigned* r, unsigned addr) {
    asm volatile("ldmatrix.sync.aligned.m8n8.x4.trans.shared.b16 {%0,%1,%2,%3}, [%4];"
                 : "=r"(r[0]), "=r"(r[1]), "=r"(r[2]), "=r"(r[3]) : "r"(addr));
}

#define CP_ASYNC16(dst, src) \
    asm volatile("cp.async.cg.shared.global [%0], [%1], 16;\n" :: "r"(dst), "l"(src))
#define CP_COMMIT()  asm volatile("cp.async.commit_group;\n")
#define CP_WAIT0()   asm volatile("cp.async.wait_group 0;\n")
#define CP_WAIT1()   asm volatile("cp.async.wait_group 1;\n")

// ============================================================================
// convert: f32 inputs/weights -> bf16 hi/lo global buffers
// ============================================================================
__global__ void __launch_bounds__(256) convert_kernel(
    const float* __restrict__ q, const float* __restrict__ k, const float* __restrict__ v,
    const float* __restrict__ wq, const float* __restrict__ wk,
    const float* __restrict__ wv, const float* __restrict__ wo)
{
    size_t i = ((size_t)blockIdx.x * 256 + threadIdx.x) * 4;
    const float* src;
    __nv_bfloat16 *dh, *dl;
    size_t off;
    if (i < (size_t)3 * XSZ) {
        int z = (int)(i / XSZ);
        off = i - (size_t)z * XSZ;
        src = (z == 0) ? q : (z == 1) ? k : v;
        dh = g_xh + (size_t)z * XSZ; dl = g_xl + (size_t)z * XSZ;
    } else {
        size_t j = i - (size_t)3 * XSZ;
        int z = (int)(j / WSZ);
        off = j - (size_t)z * WSZ;
        src = (z == 0) ? wq : (z == 1) ? wk : (z == 2) ? wv : wo;
        dh = g_wh + (size_t)z * WSZ; dl = g_wl + (size_t)z * WSZ;
    }
    float4 val = *(const float4*)(src + off);
    __nv_bfloat16 h0, l0, h1, l1, h2, l2, h3, l3;
    splitf(val.x, h0, l0); splitf(val.y, h1, l1);
    splitf(val.z, h2, l2); splitf(val.w, h3, l3);
    uint2 uh = { packh(h0, h1), packh(h2, h3) };
    uint2 ul = { packh(l0, l1), packh(l2, l3) };
    *(uint2*)(dh + off) = uh;
    *(uint2*)(dl + off) = ul;
}

// ============================================================================
// GEMM (byte-identical to R8 best): Y = X @ W^T + b, bf16 hi/lo 3-term.
// Tile 128x128, 256 threads, BK=32, 3-stage cp.async, ONE barrier/K-iter,
// XOR-swizzled smem, 2 CTAs/SM. Grid mapping: blockIdx (direct).
// ============================================================================
constexpr int G_ARR_B   = 128 * 64;            // 8192 bytes per array
constexpr int G_STAGE_B = 4 * G_ARR_B;         // 32768 bytes per stage
constexpr int GEMM_SMEM = 3 * G_STAGE_B;       // 98304 bytes

template<int MODE>
__global__ void __launch_bounds__(256, 2) gemm_kernel(
    const __nv_bfloat16* __restrict__ Ahg, const __nv_bfloat16* __restrict__ Alg,
    const __nv_bfloat16* __restrict__ Whg, const __nv_bfloat16* __restrict__ Wlg,
    const float* __restrict__ b0p, const float* __restrict__ b1p, const float* __restrict__ b2p,
    __nv_bfloat16* __restrict__ Yh, __nv_bfloat16* __restrict__ Yl,
    float* __restrict__ Yf)
{
    extern __shared__ __nv_bfloat16 gsm[];
    const unsigned smb = smem_u32(gsm);

    const int z = (MODE == 0) ? blockIdx.z : 0;
    const __nv_bfloat16* Ah = Ahg + (size_t)z * XSZ;
    const __nv_bfloat16* Al = Alg + (size_t)z * XSZ;
    const __nv_bfloat16* Bh = Whg + (size_t)z * WSZ;
    const __nv_bfloat16* Bl = Wlg + (size_t)z * WSZ;
    const float* bias = (z == 0) ? b0p : (z == 1) ? b1p : b2p;

    const int t    = threadIdx.x;
    const int w    = t >> 5;
    const int lane = t & 31;
    const int g    = lane >> 2;
    const int tg   = lane & 3;
    const int lm   = lane >> 3;   // ldmatrix matrix id (0..3)
    const int lr   = lane & 7;    // ldmatrix row-in-matrix
    const int wm   = w >> 1;      // 0..3
    const int wn   = w & 1;       // 0..1
    const int m0   = blockIdx.y * 128;
    const int n0   = blockIdx.x * 128;

    unsigned aoff[2], axor[2], boff[4], bxor[4];
    const unsigned aC = (unsigned)(lm >> 1);
    const unsigned bC = (unsigned)(lm & 1);
#pragma unroll
    for (int mi = 0; mi < 2; mi++) {
        int r = wm * 32 + mi * 16 + ((lm & 1) << 3) + lr;
        aoff[mi] = (unsigned)r * 64u;
        axor[mi] = (unsigned)((r >> 1) & 3);
    }
#pragma unroll
    for (int p = 0; p < 4; p++) {
        int r = wn * 64 + p * 16 + ((lm >> 1) << 3) + lr;
        boff[p] = (unsigned)r * 64u;
        bxor[p] = (unsigned)((r >> 1) & 3);
    }

    float acc[2][8][4];
#pragma unroll
    for (int mi = 0; mi < 2; mi++)
#pragma unroll
        for (int ni = 0; ni < 8; ni++)
#pragma unroll
            for (int j = 0; j < 4; j++) acc[mi][ni][j] = 0.f;

    auto issue_stage = [&](int kt, int stg) {
        const unsigned base = (unsigned)(stg * G_STAGE_B);
#pragma unroll
        for (int i = 0; i < 8; i++) {
            int id = t + i * 256;
            int a_ = id >> 9;                 // array 0..3
            int cid = id & 511;
            int row = cid >> 2, c = cid & 3;
            const __nv_bfloat16* gp =
                (a_ == 0) ? Ah : (a_ == 1) ? Al : (a_ == 2) ? Bh : Bl;
            const int r0 = (a_ < 2) ? m0 : n0;
            unsigned dst = smb + base + (unsigned)a_ * G_ARR_B
                         + (unsigned)row * 64u
                         + ((unsigned)(c ^ ((row >> 1) & 3)) << 4);
            CP_ASYNC16(dst, gp + (size_t)(r0 + row) * 1024 + (size_t)kt * 32 + c * 8);
        }
        CP_COMMIT();
    };

    issue_stage(0, 0);
    issue_stage(1, 1);

    for (int kt = 0; kt < 32; kt++) {
        if (kt < 31) CP_WAIT1(); else CP_WAIT0();
        __syncthreads();          // tile kt ready AND compute of kt-1 done

        if (kt + 2 < 32) issue_stage(kt + 2, (kt + 2) % 3);

        const unsigned sb = smb + (unsigned)((kt % 3) * G_STAGE_B);
#pragma unroll
        for (int kk2 = 0; kk2 < 2; kk2++) {
            unsigned ah[2][4], al[2][4], bh[4][4], bl[4][4];
#pragma unroll
            for (int mi = 0; mi < 2; mi++) {
                unsigned cidx = (((unsigned)(2 * kk2) + aC) ^ axor[mi]) << 4;
                ldsm_x4(ah[mi], sb + aoff[mi] + cidx);
                ldsm_x4(al[mi], sb + G_ARR_B + aoff[mi] + cidx);
            }
#pragma unroll
            for (int p = 0; p < 4; p++) {
                unsigned cidx = (((unsigned)(2 * kk2) + bC) ^ bxor[p]) << 4;
                ldsm_x4(bh[p], sb + 2 * G_ARR_B + boff[p] + cidx);
                ldsm_x4(bl[p], sb + 3 * G_ARR_B + boff[p] + cidx);
            }
#pragma unroll
            for (int ni = 0; ni < 8; ni++) {
                const int p = ni >> 1, ix = (ni & 1) * 2;
                unsigned b0h = bh[p][ix], b1h = bh[p][ix + 1];
                unsigned b0l = bl[p][ix], b1l = bl[p][ix + 1];
#pragma unroll
                for (int mi = 0; mi < 2; mi++) {
                    mma16816(acc[mi][ni], ah[mi], b0h, b1h);
                    mma16816(acc[mi][ni], ah[mi], b0l, b1l);
                    mma16816(acc[mi][ni], al[mi], b0h, b1h);
                }
            }
        }
    }

    // ---- epilogue ----
    const size_t zoff = (size_t)z * NQKV;
#pragma unroll
    for (int mi = 0; mi < 2; mi++) {
#pragma unroll
        for (int ni = 0; ni < 8; ni++) {
            int r = m0 + wm * 32 + mi * 16 + g;
            int c = n0 + wn * 64 + ni * 8 + tg * 2;
            float b0 = bias[c], b1 = bias[c + 1];
            float v00 = acc[mi][ni][0] + b0;
            float v01 = acc[mi][ni][1] + b1;
            float v10 = acc[mi][ni][2] + b0;
            float v11 = acc[mi][ni][3] + b1;
            if (MODE == 0) {
                int bb = r >> 11, ss = r & 2047;
                int hh = c >> 6, d = c & 63;
                size_t i0 = zoff + ((size_t)(bb * H_ + hh) * S_ + ss) * DK_ + d;
                size_t i1 = zoff + ((size_t)(bb * H_ + hh) * S_ + (ss + 8)) * DK_ + d;
                __nv_bfloat16 h0, l0, h1, l1;
                splitf(v00, h0, l0); splitf(v01, h1, l1);
                *(unsigned*)&Yh[i0] = packh(h0, h1);
                *(unsigned*)&Yl[i0] = packh(l0, l1);
                splitf(v10, h0, l0); splitf(v11, h1, l1);
                *(unsigned*)&Yh[i1] = packh(h0, h1);
                *(unsigned*)&Yl[i1] = packh(l0, l1);
            } else {
                Yf[(size_t)r * 1024 + c]           = v00;
                Yf[(size_t)r * 1024 + c + 1]       = v01;
                Yf[(size_t)(r + 8) * 1024 + c]     = v10;
                Yf[(size_t)(r + 8) * 1024 + c + 1] = v11;
            }
        }
    }
}

// ============================================================================
// Flash attention (causal), DK=64, Q-tile 128 (8 warps x 16 rows), KV-tile 64.
// CHANGE vs R8: cp.async pipeline depth 2 -> 3 stages (GEMM-proven pattern:
// wait_group 1, issue kt+2 into stage (kt+2)%3 after the top barrier).
// Everything else byte-identical to R8.
// ============================================================================
constexpr int ALD = 72;
constexpr int A_ARR = 64 * ALD;         // 4608 elems per array
constexpr int STAGE = 4 * A_ARR;        // Kh,Kl,Vh,Vl
constexpr int ATTN_SMEM = 3 * STAGE * 2;   // 110592 bytes

__global__ void __launch_bounds__(256, 1) attn_kernel(
    const __nv_bfloat16* __restrict__ Gh, const __nv_bfloat16* __restrict__ Gl,
    __nv_bfloat16* __restrict__ Ch, __nv_bfloat16* __restrict__ Cl)
{
    extern __shared__ __nv_bfloat16 sm[];

    const int qt   = (int)gridDim.x - 1 - (int)blockIdx.x;  // heavy first
    const int bh   = blockIdx.y;
    const int t    = threadIdx.x;
    const int w    = t >> 5;
    const int lane = t & 31;
    const int g    = lane >> 2;
    const int tg   = lane & 3;
    const int lm   = lane >> 3;
    const int lr   = lane & 7;

    const size_t hb = (size_t)bh * S_ * DK_;
    const __nv_bfloat16* Qhb = Gh + hb;
    const __nv_bfloat16* Qlb = Gl + hb;
    const __nv_bfloat16* Khb = Gh + NQKV + hb;
    const __nv_bfloat16* Klb = Gl + NQKV + hb;
    const __nv_bfloat16* Vhb = Gh + 2 * NQKV + hb;
    const __nv_bfloat16* Vlb = Gl + 2 * NQKV + hb;

    const unsigned smb = smem_u32(sm);
    const float NEG = -1e30f;

    const int kbase = lr * ALD + (lm << 3);
    const int vbase = (((lm & 1) << 3) + lr) * ALD + ((lm >> 1) << 3);

    unsigned qh[4][4], ql[4][4];
    {
        size_t r0 = (size_t)(qt * 128 + w * 16 + g) * DK_;
        size_t r1 = r0 + 8 * DK_;
#pragma unroll
        for (int kk = 0; kk < 4; kk++) {
            int c = kk * 16 + tg * 2;
            qh[kk][0] = *(const unsigned*)&Qhb[r0 + c];
            qh[kk][1] = *(const unsigned*)&Qhb[r1 + c];
            qh[kk][2] = *(const unsigned*)&Qhb[r0 + c + 8];
            qh[kk][3] = *(const unsigned*)&Qhb[r1 + c + 8];
            ql[kk][0] = *(const unsigned*)&Qlb[r0 + c];
            ql[kk][1] = *(const unsigned*)&Qlb[r1 + c];
            ql[kk][2] = *(const unsigned*)&Qlb[r0 + c + 8];
            ql[kk][3] = *(const unsigned*)&Qlb[r1 + c + 8];
        }
    }

    auto issue_tile = [&](int kt, int stg) {
#pragma unroll
        for (int i = 0; i < 8; i++) {
            int id = t + i * 256;
            int a_ = id >> 9;
            int cid = id & 511;
            int row = cid >> 3, seg = cid & 7;
            const __nv_bfloat16* gp =
                (a_ == 0) ? Khb : (a_ == 1) ? Klb : (a_ == 2) ? Vhb : Vlb;
            unsigned dst = smb + (unsigned)(stg * STAGE + a_ * A_ARR + row * ALD + seg * 8) * 2;
            CP_ASYNC16(dst, gp + (size_t)(kt * 64 + row) * DK_ + seg * 8);
        }
        CP_COMMIT();
    };

    float m0v = NEG, m1v = NEG, l0v = 0.f, l1v = 0.f;
    float o[8][4];
#pragma unroll
    for (int ni = 0; ni < 8; ni++)
#pragma unroll
        for (int j = 0; j < 4; j++) o[ni][j] = 0.f;

    const int ktmax = 2 * qt + 2;     // always >= 2
    issue_tile(0, 0);
    issue_tile(1, 1);

    for (int kt = 0; kt < ktmax; kt++) {
        if (kt < ktmax - 1) CP_WAIT1(); else CP_WAIT0();
        __syncthreads();      // tile kt ready AND compute of kt-1 done

        if (kt + 2 < ktmax) issue_tile(kt + 2, (kt + 2) % 3);

        const unsigned sb = (unsigned)((kt % 3) * STAGE);

        float sc_[8][4];
#pragma unroll
        for (int ni = 0; ni < 8; ni++) {
#pragma unroll
            for (int j = 0; j < 4; j++) sc_[ni][j] = 0.f;
            unsigned kh[2][4], kl[2][4];
#pragma unroll
            for (int q = 0; q < 2; q++) {
                unsigned off = sb + ni * 8 * ALD + q * 32 + kbase;
                ldsm_x4(kh[q], smb + off * 2);
                ldsm_x4(kl[q], smb + (off + A_ARR) * 2);
            }
#pragma unroll
            for (int kk = 0; kk < 4; kk++) {
                const int q = kk >> 1, ix = (kk & 1) * 2;
                unsigned b0h = kh[q][ix], b1h = kh[q][ix + 1];
                unsigned b0l = kl[q][ix], b1l = kl[q][ix + 1];
                mma16816(sc_[ni], qh[kk], b0h, b1h);
                mma16816(sc_[ni], qh[kk], b0l, b1l);
                mma16816(sc_[ni], ql[kk], b0h, b1h);
            }
        }

        const float scale = 0.125f;
        const int rA = qt * 128 + w * 16 + g;
        const int rB = rA + 8;
        if (kt * 64 + 63 > qt * 128 + w * 16) {
#pragma unroll
            for (int ni = 0; ni < 8; ni++) {
                int c0 = kt * 64 + ni * 8 + tg * 2;
                sc_[ni][0] = (c0     > rA) ? NEG : sc_[ni][0] * scale;
                sc_[ni][1] = (c0 + 1 > rA) ? NEG : sc_[ni][1] * scale;
                sc_[ni][2] = (c0     > rB) ? NEG : sc_[ni][2] * scale;
                sc_[ni][3] = (c0 + 1 > rB) ? NEG : sc_[ni][3] * scale;
            }
        } else {
#pragma unroll
            for (int ni = 0; ni < 8; ni++)
#pragma unroll
                for (int j = 0; j < 4; j++) sc_[ni][j] *= scale;
        }

        float mx0 = NEG, mx1 = NEG;
#pragma unroll
        for (int ni = 0; ni < 8; ni++) {
            mx0 = fmaxf(mx0, fmaxf(sc_[ni][0], sc_[ni][1]));
            mx1 = fmaxf(mx1, fmaxf(sc_[ni][2], sc_[ni][3]));
        }
        mx0 = fmaxf(mx0, __shfl_xor_sync(0xffffffffu, mx0, 1));
        mx0 = fmaxf(mx0, __shfl_xor_sync(0xffffffffu, mx0, 2));
        mx1 = fmaxf(mx1, __shfl_xor_sync(0xffffffffu, mx1, 1));
        mx1 = fmaxf(mx1, __shfl_xor_sync(0xffffffffu, mx1, 2));

        float nm0 = fmaxf(m0v, mx0), nm1 = fmaxf(m1v, mx1);
        float corr0 = __expf(m0v - nm0), corr1 = __expf(m1v - nm1);

        float sum0 = 0.f, sum1 = 0.f;
#pragma unroll
        for (int ni = 0; ni < 8; ni++) {
            sc_[ni][0] = __expf(sc_[ni][0] - nm0);
            sc_[ni][1] = __expf(sc_[ni][1] - nm0);
            sc_[ni][2] = __expf(sc_[ni][2] - nm1);
            sc_[ni][3] = __expf(sc_[ni][3] - nm1);
            sum0 += sc_[ni][0] + sc_[ni][1];
            sum1 += sc_[ni][2] + sc_[ni][3];
        }
        sum0 += __shfl_xor_sync(0xffffffffu, sum0, 1);
        sum0 += __shfl_xor_sync(0xffffffffu, sum0, 2);
        sum1 += __shfl_xor_sync(0xffffffffu, sum1, 1);
        sum1 += __shfl_xor_sync(0xffffffffu, sum1, 2);

        l0v = l0v * corr0 + sum0;
        l1v = l1v * corr1 + sum1;
        m0v = nm0; m1v = nm1;

#pragma unroll
        for (int ni = 0; ni < 8; ni++) {
            o[ni][0] *= corr0; o[ni][1] *= corr0;
            o[ni][2] *= corr1; o[ni][3] *= corr1;
        }

#pragma unroll
        for (int j = 0; j < 4; j++) {
            unsigned ah[4], al[4];
            {
                __nv_bfloat16 h0, l0, h1, l1;
                splitf(sc_[2 * j][0], h0, l0); splitf(sc_[2 * j][1], h1, l1);
                ah[0] = packh(h0, h1); al[0] = packh(l0, l1);
                splitf(sc_[2 * j][2], h0, l0); splitf(sc_[2 * j][3], h1, l1);
                ah[1] = packh(h0, h1); al[1] = packh(l0, l1);
                splitf(sc_[2 * j + 1][0], h0, l0); splitf(sc_[2 * j + 1][1], h1, l1);
                ah[2] = packh(h0, h1); al[2] = packh(l0, l1);
                splitf(sc_[2 * j + 1][2], h0, l0); splitf(sc_[2 * j + 1][3], h1, l1);
                ah[3] = packh(h0, h1); al[3] = packh(l0, l1);
            }
            unsigned vh[4][4], vl[4][4];
#pragma unroll
            for (int p = 0; p < 4; p++) {
                unsigned off = sb + 2 * A_ARR + j * 16 * ALD + p * 16 + vbase;
                ldsm_x4t(vh[p], smb + off * 2);
                ldsm_x4t(vl[p], smb + (off + A_ARR) * 2);
            }
#pragma unroll
            for (int ni = 0; ni < 8; ni++) {
                const int p = ni >> 1, ix = (ni & 1) * 2;
                unsigned b0h = vh[p][ix], b1h = vh[p][ix + 1];
                unsigned b0l = vl[p][ix], b1l = vl[p][ix + 1];
                mma16816(o[ni], ah, b0h, b1h);
                mma16816(o[ni], ah, b0l, b1l);
                mma16816(o[ni], al, b0h, b1h);
            }
        }
    }

    float inv0 = 1.f / l0v, inv1 = 1.f / l1v;
    int bb = bh >> 4, hh = bh & 15;
    int q0 = qt * 128 + w * 16 + g;
#pragma unroll
    for (int ni = 0; ni < 8; ni++) {
        int d = ni * 8 + tg * 2;
        size_t i0 = ((size_t)(bb * S_ + q0)) * D_ + hh * 64 + d;
        size_t i1 = ((size_t)(bb * S_ + q0 + 8)) * D_ + hh * 64 + d;
        __nv_bfloat16 h0, l0, h1, l1;
        splitf(o[ni][0] * inv0, h0, l0); splitf(o[ni][1] * inv0, h1, l1);
        *(unsigned*)&Ch[i0] = packh(h0, h1);
        *(unsigned*)&Cl[i0] = packh(l0, l1);
        splitf(o[ni][2] * inv1, h0, l0); splitf(o[ni][3] * inv1, h1, l1);
        *(unsigned*)&Ch[i1] = packh(h0, h1);
        *(unsigned*)&Cl[i1] = packh(l0, l1);
    }
}

// ============================================================================
// Launch
// ============================================================================
extern "C" void kernel_launch(void* const* d_in, const int* in_sizes, int n_in,
                              void* d_out, int out_size)
{
    const float* q  = (const float*)d_in[0];
    const float* k  = (const float*)d_in[1];
    const float* v  = (const float*)d_in[2];
    const float* wq = (const float*)d_in[4];
    const float* bq = (const float*)d_in[5];
    const float* wk = (const float*)d_in[6];
    const float* bk = (const float*)d_in[7];
    const float* wv = (const float*)d_in[8];
    const float* bv = (const float*)d_in[9];
    const float* wo = (const float*)d_in[10];
    const float* bo = (const float*)d_in[11];
    float* out = (float*)d_out;

    __nv_bfloat16 *gxh, *gxl, *gwh, *gwl, *gh, *gl, *gch, *gcl;
    cudaGetSymbolAddress((void**)&gxh, g_xh);
    cudaGetSymbolAddress((void**)&gxl, g_xl);
    cudaGetSymbolAddress((void**)&gwh, g_wh);
    cudaGetSymbolAddress((void**)&gwl, g_wl);
    cudaGetSymbolAddress((void**)&gh,  g_h);
    cudaGetSymbolAddress((void**)&gl,  g_l);
    cudaGetSymbolAddress((void**)&gch, g_ch);
    cudaGetSymbolAddress((void**)&gcl, g_cl);

    cudaFuncSetAttribute(gemm_kernel<0>,
                         cudaFuncAttributeMaxDynamicSharedMemorySize, GEMM_SMEM);
    cudaFuncSetAttribute(gemm_kernel<1>,
                         cudaFuncAttributeMaxDynamicSharedMemorySize, GEMM_SMEM);
    cudaFuncSetAttribute(attn_kernel,
                         cudaFuncAttributeMaxDynamicSharedMemorySize, ATTN_SMEM);

    // 1) split inputs + weights to bf16 hi/lo
    convert_kernel<<<16384, 256>>>(q, k, v, wq, wk, wv, wo);

    // 2) QKV projections (R8 grid mapping)
    gemm_kernel<0><<<dim3(8, 32, 3), 256, GEMM_SMEM>>>(
        gxh, gxl, gwh, gwl, bq, bk, bv, gh, gl, nullptr);

    // 3) attention (3-stage pipeline)
    attn_kernel<<<dim3(S_ / 128, B_ * H_), 256, ATTN_SMEM>>>(gh, gl, gch, gcl);

    // 4) output projection (R8 mapping)
    gemm_kernel<1><<<dim3(8, 32, 1), 256, GEMM_SMEM>>>(
        gch, gcl, gwh + 3 * WSZ, gwl + 3 * WSZ, bo, bo, bo, nullptr, nullptr, out);
}

// round 15
// speedup vs baseline: 1.0554x; 1.0090x over previous
#include <cuda_runtime.h>
#include <cuda_bf16.h>
#include <cstdint>

#define DINLINE __device__ __forceinline__

constexpr int B_  = 2;
constexpr int S_  = 2048;
constexpr int D_  = 1024;
constexpr int H_  = 16;
constexpr int DK_ = 64;

constexpr size_t NQKV = (size_t)B_ * H_ * S_ * DK_;   // 4M elems
constexpr size_t XSZ  = (size_t)4096 * 1024;          // 4M
constexpr size_t WSZ  = (size_t)1024 * 1024;          // 1M

// ---------------- global scratch ----------------
__device__ __nv_bfloat16 g_xh[3 * XSZ], g_xl[3 * XSZ];     // q,k,v inputs split
__device__ __nv_bfloat16 g_wh[4 * WSZ], g_wl[4 * WSZ];     // wq,wk,wv,wo split
__device__ __nv_bfloat16 g_h[3 * NQKV], g_l[3 * NQKV];     // Q,K,V proj [B,H,S,DK]
__device__ __nv_bfloat16 g_ch[XSZ], g_cl[XSZ];             // attn context split

// ---------------- helpers ----------------
DINLINE unsigned packh(__nv_bfloat16 a, __nv_bfloat16 b) {
    __nv_bfloat162 v; v.x = a; v.y = b;
    return *reinterpret_cast<unsigned*>(&v);
}
DINLINE void splitf(float x, __nv_bfloat16& h, __nv_bfloat16& l) {
    h = __float2bfloat16(x);
    l = __float2bfloat16(x - __bfloat162float(h));
}
DINLINE void mma16816(float* c, const unsigned* a, unsigned b0, unsigned b1) {
    asm volatile(
        "mma.sync.aligned.m16n8k16.row.col.f32.bf16.bf16.f32 "
        "{%0,%1,%2,%3},{%4,%5,%6,%7},{%8,%9},{%0,%1,%2,%3};\n"
        : "+f"(c[0]), "+f"(c[1]), "+f"(c[2]), "+f"(c[3])
        : "r"(a[0]), "r"(a[1]), "r"(a[2]), "r"(a[3]), "r"(b0), "r"(b1));
}
DINLINE unsigned smem_u32(const void* p) {
    unsigned a;
    asm("{.reg .u64 t; cvta.to.shared.u64 t, %1; cvt.u32.u64 %0, t;}" : "=r"(a) : "l"(p));
    return a;
}
DINLINE void ldsm_x4(unsigned* r, unsigned addr) {
    asm volatile("ldmatrix.sync.aligned.m8n8.x4.shared.b16 {%0,%1,%2,%3}, [%4];"
                 : "=r"(r[0]), "=r"(r[1]), "=r"(r[2]), "=r"(r[3]) : "r"(addr));
}
DINLINE void ldsm_x4t(unsigned* r, unsigned addr) {
    asm volatile("ldmatrix.sync.aligned.m8n8.x4.trans.shared.b16 {%0,%1,%2,%3}, [%4];"
                 : "=r"(r[0]), "=r"(r[1]), "=r"(r[2]), "=r"(r[3]) : "r"(addr));
}

#define CP_ASYNC16(dst, src) \
    asm volatile("cp.async.cg.shared.global [%0], [%1], 16;\n" :: "r"(dst), "l"(src))
#define CP_COMMIT()  asm volatile("cp.async.commit_group;\n")
#define CP_WAIT0()   asm volatile("cp.async.wait_group 0;\n")
#define CP_WAIT1()   asm volatile("cp.async.wait_group 1;\n")

// ============================================================================
// convert: f32 inputs/weights -> bf16 hi/lo global buffers
// ============================================================================
__global__ void __launch_bounds__(256) convert_kernel(
    const float* __restrict__ q, const float* __restrict__ k, const float* __restrict__ v,
    const float* __restrict__ wq, const float* __restrict__ wk,
    const float* __restrict__ wv, const float* __restrict__ wo)
{
    size_t i = ((size_t)blockIdx.x * 256 + threadIdx.x) * 4;
    const float* src;
    __nv_bfloat16 *dh, *dl;
    size_t off;
    if (i < (size_t)3 * XSZ) {
        int z = (int)(i / XSZ);
        off = i - (size_t)z * XSZ;
        src = (z == 0) ? q : (z == 1) ? k : v;
        dh = g_xh + (size_t)z * XSZ; dl = g_xl + (size_t)z * XSZ;
    } else {
        size_t j = i - (size_t)3 * XSZ;
        int z = (int)(j / WSZ);
        off = j - (size_t)z * WSZ;
        src = (z == 0) ? wq : (z == 1) ? wk : (z == 2) ? wv : wo;
        dh = g_wh + (size_t)z * WSZ; dl = g_wl + (size_t)z * WSZ;
    }
    float4 val = *(const float4*)(src + off);
    __nv_bfloat16 h0, l0, h1, l1, h2, l2, h3, l3;
    splitf(val.x, h0, l0); splitf(val.y, h1, l1);
    splitf(val.z, h2, l2); splitf(val.w, h3, l3);
    uint2 uh = { packh(h0, h1), packh(h2, h3) };
    uint2 ul = { packh(l0, l1), packh(l2, l3) };
    *(uint2*)(dh + off) = uh;
    *(uint2*)(dl + off) = ul;
}

// ============================================================================
// GEMM (R8 best): Y = X @ W^T + b, bf16 hi/lo 3-term.
// Tile 128x128, 256 threads, BK=32, 3-stage cp.async, ONE barrier/K-iter,
// XOR-swizzled smem, 2 CTAs/SM. Grid mapping: blockIdx (direct).
// MODE 0 z==0 (Q projection) pre-scales output by 1/8 so attention
// needs no per-tile scale.
// ============================================================================
constexpr int G_ARR_B   = 128 * 64;            // 8192 bytes per array
constexpr int G_STAGE_B = 4 * G_ARR_B;         // 32768 bytes per stage
constexpr int GEMM_SMEM = 3 * G_STAGE_B;       // 98304 bytes

template<int MODE>
__global__ void __launch_bounds__(256, 2) gemm_kernel(
    const __nv_bfloat16* __restrict__ Ahg, const __nv_bfloat16* __restrict__ Alg,
    const __nv_bfloat16* __restrict__ Whg, const __nv_bfloat16* __restrict__ Wlg,
    const float* __restrict__ b0p, const float* __restrict__ b1p, const float* __restrict__ b2p,
    __nv_bfloat16* __restrict__ Yh, __nv_bfloat16* __restrict__ Yl,
    float* __restrict__ Yf)
{
    extern __shared__ __nv_bfloat16 gsm[];
    const unsigned smb = smem_u32(gsm);

    const int z = (MODE == 0) ? blockIdx.z : 0;
    const __nv_bfloat16* Ah = Ahg + (size_t)z * XSZ;
    const __nv_bfloat16* Al = Alg + (size_t)z * XSZ;
    const __nv_bfloat16* Bh = Whg + (size_t)z * WSZ;
    const __nv_bfloat16* Bl = Wlg + (size_t)z * WSZ;
    const float* bias = (z == 0) ? b0p : (z == 1) ? b1p : b2p;

    const int t    = threadIdx.x;
    const int w    = t >> 5;
    const int lane = t & 31;
    const int g    = lane >> 2;
    const int tg   = lane & 3;
    const int lm   = lane >> 3;   // ldmatrix matrix id (0..3)
    const int lr   = lane & 7;    // ldmatrix row-in-matrix
    const int wm   = w >> 1;      // 0..3
    const int wn   = w & 1;       // 0..1
    const int m0   = blockIdx.y * 128;
    const int n0   = blockIdx.x * 128;

    unsigned aoff[2], axor[2], boff[4], bxor[4];
    const unsigned aC = (unsigned)(lm >> 1);
    const unsigned bC = (unsigned)(lm & 1);
#pragma unroll
    for (int mi = 0; mi < 2; mi++) {
        int r = wm * 32 + mi * 16 + ((lm & 1) << 3) + lr;
        aoff[mi] = (unsigned)r * 64u;
        axor[mi] = (unsigned)((r >> 1) & 3);
    }
#pragma unroll
    for (int p = 0; p < 4; p++) {
        int r = wn * 64 + p * 16 + ((lm >> 1) << 3) + lr;
        boff[p] = (unsigned)r * 64u;
        bxor[p] = (unsigned)((r >> 1) & 3);
    }

    float acc[2][8][4];
#pragma unroll
    for (int mi = 0; mi < 2; mi++)
#pragma unroll
        for (int ni = 0; ni < 8; ni++)
#pragma unroll
            for (int j = 0; j < 4; j++) acc[mi][ni][j] = 0.f;

    auto issue_stage = [&](int kt, int stg) {
        const unsigned base = (unsigned)(stg * G_STAGE_B);
#pragma unroll
        for (int i = 0; i < 8; i++) {
            int id = t + i * 256;
            int a_ = id >> 9;                 // array 0..3
            int cid = id & 511;
            int row = cid >> 2, c = cid & 3;
            const __nv_bfloat16* gp =
                (a_ == 0) ? Ah : (a_ == 1) ? Al : (a_ == 2) ? Bh : Bl;
            const int r0 = (a_ < 2) ? m0 : n0;
            unsigned dst = smb + base + (unsigned)a_ * G_ARR_B
                         + (unsigned)row * 64u
                         + ((unsigned)(c ^ ((row >> 1) & 3)) << 4);
            CP_ASYNC16(dst, gp + (size_t)(r0 + row) * 1024 + (size_t)kt * 32 + c * 8);
        }
        CP_COMMIT();
    };

    issue_stage(0, 0);
    issue_stage(1, 1);

    for (int kt = 0; kt < 32; kt++) {
        if (kt < 31) CP_WAIT1(); else CP_WAIT0();
        __syncthreads();          // tile kt ready AND compute of kt-1 done

        if (kt + 2 < 32) issue_stage(kt + 2, (kt + 2) % 3);

        const unsigned sb = smb + (unsigned)((kt % 3) * G_STAGE_B);
#pragma unroll
        for (int kk2 = 0; kk2 < 2; kk2++) {
            unsigned ah[2][4], al[2][4], bh[4][4], bl[4][4];
#pragma unroll
            for (int mi = 0; mi < 2; mi++) {
                unsigned cidx = (((unsigned)(2 * kk2) + aC) ^ axor[mi]) << 4;
                ldsm_x4(ah[mi], sb + aoff[mi] + cidx);
                ldsm_x4(al[mi], sb + G_ARR_B + aoff[mi] + cidx);
            }
#pragma unroll
            for (int p = 0; p < 4; p++) {
                unsigned cidx = (((unsigned)(2 * kk2) + bC) ^ bxor[p]) << 4;
                ldsm_x4(bh[p], sb + 2 * G_ARR_B + boff[p] + cidx);
                ldsm_x4(bl[p], sb + 3 * G_ARR_B + boff[p] + cidx);
            }
#pragma unroll
            for (int ni = 0; ni < 8; ni++) {
                const int p = ni >> 1, ix = (ni & 1) * 2;
                unsigned b0h = bh[p][ix], b1h = bh[p][ix + 1];
                unsigned b0l = bl[p][ix], b1l = bl[p][ix + 1];
#pragma unroll
                for (int mi = 0; mi < 2; mi++) {
                    mma16816(acc[mi][ni], ah[mi], b0h, b1h);
                    mma16816(acc[mi][ni], ah[mi], b0l, b1l);
                    mma16816(acc[mi][ni], al[mi], b0h, b1h);
                }
            }
        }
    }

    // ---- epilogue ----
    const size_t zoff = (size_t)z * NQKV;
    const float osc = (MODE == 0 && z == 0) ? 0.125f : 1.0f;  // pre-scale Q
#pragma unroll
    for (int mi = 0; mi < 2; mi++) {
#pragma unroll
        for (int ni = 0; ni < 8; ni++) {
            int r = m0 + wm * 32 + mi * 16 + g;
            int c = n0 + wn * 64 + ni * 8 + tg * 2;
            float b0 = bias[c], b1 = bias[c + 1];
            float v00 = (acc[mi][ni][0] + b0) * osc;
            float v01 = (acc[mi][ni][1] + b1) * osc;
            float v10 = (acc[mi][ni][2] + b0) * osc;
            float v11 = (acc[mi][ni][3] + b1) * osc;
            if (MODE == 0) {
                int bb = r >> 11, ss = r & 2047;
                int hh = c >> 6, d = c & 63;
                size_t i0 = zoff + ((size_t)(bb * H_ + hh) * S_ + ss) * DK_ + d;
                size_t i1 = zoff + ((size_t)(bb * H_ + hh) * S_ + (ss + 8)) * DK_ + d;
                __nv_bfloat16 h0, l0, h1, l1;
                splitf(v00, h0, l0); splitf(v01, h1, l1);
                *(unsigned*)&Yh[i0] = packh(h0, h1);
                *(unsigned*)&Yl[i0] = packh(l0, l1);
                splitf(v10, h0, l0); splitf(v11, h1, l1);
                *(unsigned*)&Yh[i1] = packh(h0, h1);
                *(unsigned*)&Yl[i1] = packh(l0, l1);
            } else {
                Yf[(size_t)r * 1024 + c]           = v00;
                Yf[(size_t)r * 1024 + c + 1]       = v01;
                Yf[(size_t)(r + 8) * 1024 + c]     = v10;
                Yf[(size_t)(r + 8) * 1024 + c + 1] = v11;
            }
        }
    }
}

// ============================================================================
// Flash attention (causal), DK=64, Q-tile 128 (8 warps x 16 rows), KV-tile 64.
// R8 2-stage pipeline. Q arrives PRE-SCALED by 1/8 -> no scale in the loop;
// non-diagonal tiles skip the mask/scale pass entirely.
// ============================================================================
constexpr int ALD = 72;
constexpr int A_ARR = 64 * ALD;         // 4608 elems per array
constexpr int STAGE = 4 * A_ARR;        // Kh,Kl,Vh,Vl
constexpr int ATTN_SMEM = 2 * STAGE * 2;

__global__ void __launch_bounds__(256, 1) attn_kernel(
    const __nv_bfloat16* __restrict__ Gh, const __nv_bfloat16* __restrict__ Gl,
    __nv_bfloat16* __restrict__ Ch, __nv_bfloat16* __restrict__ Cl)
{
    extern __shared__ __nv_bfloat16 sm[];

    const int qt   = (int)gridDim.x - 1 - (int)blockIdx.x;  // heavy first
    const int bh   = blockIdx.y;
    const int t    = threadIdx.x;
    const int w    = t >> 5;
    const int lane = t & 31;
    const int g    = lane >> 2;
    const int tg   = lane & 3;
    const int lm   = lane >> 3;
    const int lr   = lane & 7;

    const size_t hb = (size_t)bh * S_ * DK_;
    const __nv_bfloat16* Qhb = Gh + hb;
    const __nv_bfloat16* Qlb = Gl + hb;
    const __nv_bfloat16* Khb = Gh + NQKV + hb;
    const __nv_bfloat16* Klb = Gl + NQKV + hb;
    const __nv_bfloat16* Vhb = Gh + 2 * NQKV + hb;
    const __nv_bfloat16* Vlb = Gl + 2 * NQKV + hb;

    const unsigned smb = smem_u32(sm);
    const float NEG = -1e30f;

    const int kbase = lr * ALD + (lm << 3);
    const int vbase = (((lm & 1) << 3) + lr) * ALD + ((lm >> 1) << 3);

    unsigned qh[4][4], ql[4][4];
    {
        size_t r0 = (size_t)(qt * 128 + w * 16 + g) * DK_;
        size_t r1 = r0 + 8 * DK_;
#pragma unroll
        for (int kk = 0; kk < 4; kk++) {
            int c = kk * 16 + tg * 2;
            qh[kk][0] = *(const unsigned*)&Qhb[r0 + c];
            qh[kk][1] = *(const unsigned*)&Qhb[r1 + c];
            qh[kk][2] = *(const unsigned*)&Qhb[r0 + c + 8];
            qh[kk][3] = *(const unsigned*)&Qhb[r1 + c + 8];
            ql[kk][0] = *(const unsigned*)&Qlb[r0 + c];
            ql[kk][1] = *(const unsigned*)&Qlb[r1 + c];
            ql[kk][2] = *(const unsigned*)&Qlb[r0 + c + 8];
            ql[kk][3] = *(const unsigned*)&Qlb[r1 + c + 8];
        }
    }

    auto issue_tile = [&](int kt, int stg) {
#pragma unroll
        for (int i = 0; i < 8; i++) {
            int id = t + i * 256;
            int a_ = id >> 9;
            int cid = id & 511;
            int row = cid >> 3, seg = cid & 7;
            const __nv_bfloat16* gp =
                (a_ == 0) ? Khb : (a_ == 1) ? Klb : (a_ == 2) ? Vhb : Vlb;
            unsigned dst = smb + (unsigned)(stg * STAGE + a_ * A_ARR + row * ALD + seg * 8) * 2;
            CP_ASYNC16(dst, gp + (size_t)(kt * 64 + row) * DK_ + seg * 8);
        }
        CP_COMMIT();
    };

    float m0v = NEG, m1v = NEG, l0v = 0.f, l1v = 0.f;
    float o[8][4];
#pragma unroll
    for (int ni = 0; ni < 8; ni++)
#pragma unroll
        for (int j = 0; j < 4; j++) o[ni][j] = 0.f;

    const int ktmax = 2 * qt + 2;
    issue_tile(0, 0);

    for (int kt = 0; kt < ktmax; kt++) {
        const int s = kt & 1;
        CP_WAIT0();
        __syncthreads();

        if (kt + 1 < ktmax) issue_tile(kt + 1, s ^ 1);

        const unsigned sb = (unsigned)(s * STAGE);

        float sc_[8][4];
#pragma unroll
        for (int ni = 0; ni < 8; ni++) {
#pragma unroll
            for (int j = 0; j < 4; j++) sc_[ni][j] = 0.f;
            unsigned kh[2][4], kl[2][4];
#pragma unroll
            for (int q = 0; q < 2; q++) {
                unsigned off = sb + ni * 8 * ALD + q * 32 + kbase;
                ldsm_x4(kh[q], smb + off * 2);
                ldsm_x4(kl[q], smb + (off + A_ARR) * 2);
            }
#pragma unroll
            for (int kk = 0; kk < 4; kk++) {
                const int q = kk >> 1, ix = (kk & 1) * 2;
                unsigned b0h = kh[q][ix], b1h = kh[q][ix + 1];
                unsigned b0l = kl[q][ix], b1l = kl[q][ix + 1];
                mma16816(sc_[ni], qh[kk], b0h, b1h);
                mma16816(sc_[ni], qh[kk], b0l, b1l);
                mma16816(sc_[ni], ql[kk], b0h, b1h);
            }
        }

        // ---- causal mask (Q pre-scaled; only the diagonal tile needs work) ----
        if (kt * 64 + 63 > qt * 128 + w * 16) {
            const int rA = qt * 128 + w * 16 + g;
            const int rB = rA + 8;
#pragma unroll
            for (int ni = 0; ni < 8; ni++) {
                int c0 = kt * 64 + ni * 8 + tg * 2;
                if (c0     > rA) sc_[ni][0] = NEG;
                if (c0 + 1 > rA) sc_[ni][1] = NEG;
                if (c0     > rB) sc_[ni][2] = NEG;
                if (c0 + 1 > rB) sc_[ni][3] = NEG;
            }
        }

        float mx0 = NEG, mx1 = NEG;
#pragma unroll
        for (int ni = 0; ni < 8; ni++) {
            mx0 = fmaxf(mx0, fmaxf(sc_[ni][0], sc_[ni][1]));
            mx1 = fmaxf(mx1, fmaxf(sc_[ni][2], sc_[ni][3]));
        }
        mx0 = fmaxf(mx0, __shfl_xor_sync(0xffffffffu, mx0, 1));
        mx0 = fmaxf(mx0, __shfl_xor_sync(0xffffffffu, mx0, 2));
        mx1 = fmaxf(mx1, __shfl_xor_sync(0xffffffffu, mx1, 1));
        mx1 = fmaxf(mx1, __shfl_xor_sync(0xffffffffu, mx1, 2));

        float nm0 = fmaxf(m0v, mx0), nm1 = fmaxf(m1v, mx1);
        float corr0 = __expf(m0v - nm0), corr1 = __expf(m1v - nm1);

        float sum0 = 0.f, sum1 = 0.f;
#pragma unroll
        for (int ni = 0; ni < 8; ni++) {
            sc_[ni][0] = __expf(sc_[ni][0] - nm0);
            sc_[ni][1] = __expf(sc_[ni][1] - nm0);
            sc_[ni][2] = __expf(sc_[ni][2] - nm1);
            sc_[ni][3] = __expf(sc_[ni][3] - nm1);
            sum0 += sc_[ni][0] + sc_[ni][1];
            sum1 += sc_[ni][2] + sc_[ni][3];
        }
        sum0 += __shfl_xor_sync(0xffffffffu, sum0, 1);
        sum0 += __shfl_xor_sync(0xffffffffu, sum0, 2);
        sum1 += __shfl_xor_sync(0xffffffffu, sum1, 1);
        sum1 += __shfl_xor_sync(0xffffffffu, sum1, 2);

        l0v = l0v * corr0 + sum0;
        l1v = l1v * corr1 + sum1;
        m0v = nm0; m1v = nm1;

#pragma unroll
        for (int ni = 0; ni < 8; ni++) {
            o[ni][0] *= corr0; o[ni][1] *= corr0;
            o[ni][2] *= corr1; o[ni][3] *= corr1;
        }

#pragma unroll
        for (int j = 0; j < 4; j++) {
            unsigned ah[4], al[4];
            {
                __nv_bfloat16 h0, l0, h1, l1;
                splitf(sc_[2 * j][0], h0, l0); splitf(sc_[2 * j][1], h1, l1);
                ah[0] = packh(h0, h1); al[0] = packh(l0, l1);
                splitf(sc_[2 * j][2], h0, l0); splitf(sc_[2 * j][3], h1, l1);
                ah[1] = packh(h0, h1); al[1] = packh(l0, l1);
                splitf(sc_[2 * j + 1][0], h0, l0); splitf(sc_[2 * j + 1][1], h1, l1);
                ah[2] = packh(h0, h1); al[2] = packh(l0, l1);
                splitf(sc_[2 * j + 1][2], h0, l0); splitf(sc_[2 * j + 1][3], h1, l1);
                ah[3] = packh(h0, h1); al[3] = packh(l0, l1);
            }
            unsigned vh[4][4], vl[4][4];
#pragma unroll
            for (int p = 0; p < 4; p++) {
                unsigned off = sb + 2 * A_ARR + j * 16 * ALD + p * 16 + vbase;
                ldsm_x4t(vh[p], smb + off * 2);
                ldsm_x4t(vl[p], smb + (off + A_ARR) * 2);
            }
#pragma unroll
            for (int ni = 0; ni < 8; ni++) {
                const int p = ni >> 1, ix = (ni & 1) * 2;
                unsigned b0h = vh[p][ix], b1h = vh[p][ix + 1];
                unsigned b0l = vl[p][ix], b1l = vl[p][ix + 1];
                mma16816(o[ni], ah, b0h, b1h);
                mma16816(o[ni], ah, b0l, b1l);
                mma16816(o[ni], al, b0h, b1h);
            }
        }
    }

    float inv0 = 1.f / l0v, inv1 = 1.f / l1v;
    int bb = bh >> 4, hh = bh & 15;
    int q0 = qt * 128 + w * 16 + g;
#pragma unroll
    for (int ni = 0; ni < 8; ni++) {
        int d = ni * 8 + tg * 2;
        size_t i0 = ((size_t)(bb * S_ + q0)) * D_ + hh * 64 + d;
        size_t i1 = ((size_t)(bb * S_ + q0 + 8)) * D_ + hh * 64 + d;
        __nv_bfloat16 h0, l0, h1, l1;
        splitf(o[ni][0] * inv0, h0, l0); splitf(o[ni][1] * inv0, h1, l1);
        *(unsigned*)&Ch[i0] = packh(h0, h1);
        *(unsigned*)&Cl[i0] = packh(l0, l1);
        splitf(o[ni][2] * inv1, h0, l0); splitf(o[ni][3] * inv1, h1, l1);
        *(unsigned*)&Ch[i1] = packh(h0, h1);
        *(unsigned*)&Cl[i1] = packh(l0, l1);
    }
}

// ============================================================================
// Launch
// ============================================================================
extern "C" void kernel_launch(void* const* d_in, const int* in_sizes, int n_in,
                              void* d_out, int out_size)
{
    const float* q  = (const float*)d_in[0];
    const float* k  = (const float*)d_in[1];
    const float* v  = (const float*)d_in[2];
    const float* wq = (const float*)d_in[4];
    const float* bq = (const float*)d_in[5];
    const float* wk = (const float*)d_in[6];
    const float* bk = (const float*)d_in[7];
    const float* wv = (const float*)d_in[8];
    const float* bv = (const float*)d_in[9];
    const float* wo = (const float*)d_in[10];
    const float* bo = (const float*)d_in[11];
    float* out = (float*)d_out;

    __nv_bfloat16 *gxh, *gxl, *gwh, *gwl, *gh, *gl, *gch, *gcl;
    cudaGetSymbolAddress((void**)&gxh, g_xh);
    cudaGetSymbolAddress((void**)&gxl, g_xl);
    cudaGetSymbolAddress((void**)&gwh, g_wh);
    cudaGetSymbolAddress((void**)&gwl, g_wl);
    cudaGetSymbolAddress((void**)&gh,  g_h);
    cudaGetSymbolAddress((void**)&gl,  g_l);
    cudaGetSymbolAddress((void**)&gch, g_ch);
    cudaGetSymbolAddress((void**)&gcl, g_cl);

    cudaFuncSetAttribute(gemm_kernel<0>,
                         cudaFuncAttributeMaxDynamicSharedMemorySize, GEMM_SMEM);
    cudaFuncSetAttribute(gemm_kernel<1>,
                         cudaFuncAttributeMaxDynamicSharedMemorySize, GEMM_SMEM);
    cudaFuncSetAttribute(attn_kernel,
                         cudaFuncAttributeMaxDynamicSharedMemorySize, ATTN_SMEM);

    // 1) split inputs + weights to bf16 hi/lo
    convert_kernel<<<16384, 256>>>(q, k, v, wq, wk, wv, wo);

    // 2) QKV projections (Q output pre-scaled by 1/8)
    gemm_kernel<0><<<dim3(8, 32, 3), 256, GEMM_SMEM>>>(
        gxh, gxl, gwh, gwl, bq, bk, bv, gh, gl, nullptr);

    // 3) attention (R8 2-stage)
    attn_kernel<<<dim3(S_ / 128, B_ * H_), 256, ATTN_SMEM>>>(gh, gl, gch, gcl);

    // 4) output projection
    gemm_kernel<1><<<dim3(8, 32, 1), 256, GEMM_SMEM>>>(
        gch, gcl, gwh + 3 * WSZ, gwl + 3 * WSZ, bo, bo, bo, nullptr, nullptr, out);
}

// round 16
// speedup vs baseline: 1.0731x; 1.0168x over previous
#include <cuda_runtime.h>
#include <cuda_bf16.h>
#include <cstdint>

#define DINLINE __device__ __forceinline__

constexpr int B_  = 2;
constexpr int S_  = 2048;
constexpr int D_  = 1024;
constexpr int H_  = 16;
constexpr int DK_ = 64;

constexpr size_t NQKV = (size_t)B_ * H_ * S_ * DK_;   // 4M elems
constexpr size_t XSZ  = (size_t)4096 * 1024;          // 4M
constexpr size_t WSZ  = (size_t)1024 * 1024;          // 1M

// ---------------- global scratch ----------------
__device__ __nv_bfloat16 g_xh[3 * XSZ], g_xl[3 * XSZ];     // q,k,v inputs split
__device__ __nv_bfloat16 g_wh[4 * WSZ], g_wl[4 * WSZ];     // wq,wk,wv,wo split
__device__ __nv_bfloat16 g_h[3 * NQKV], g_l[3 * NQKV];     // Q,K,V proj [B,H,S,DK]
__device__ __nv_bfloat16 g_ch[XSZ], g_cl[XSZ];             // attn context split

// ---------------- helpers ----------------
DINLINE unsigned packh(__nv_bfloat16 a, __nv_bfloat16 b) {
    __nv_bfloat162 v; v.x = a; v.y = b;
    return *reinterpret_cast<unsigned*>(&v);
}
DINLINE void splitf(float x, __nv_bfloat16& h, __nv_bfloat16& l) {
    h = __float2bfloat16(x);
    l = __float2bfloat16(x - __bfloat162float(h));
}
DINLINE void mma16816(float* c, const unsigned* a, unsigned b0, unsigned b1) {
    asm volatile(
        "mma.sync.aligned.m16n8k16.row.col.f32.bf16.bf16.f32 "
        "{%0,%1,%2,%3},{%4,%5,%6,%7},{%8,%9},{%0,%1,%2,%3};\n"
        : "+f"(c[0]), "+f"(c[1]), "+f"(c[2]), "+f"(c[3])
        : "r"(a[0]), "r"(a[1]), "r"(a[2]), "r"(a[3]), "r"(b0), "r"(b1));
}
DINLINE unsigned smem_u32(const void* p) {
    unsigned a;
    asm("{.reg .u64 t; cvta.to.shared.u64 t, %1; cvt.u32.u64 %0, t;}" : "=r"(a) : "l"(p));
    return a;
}
DINLINE void ldsm_x4(unsigned* r, unsigned addr) {
    asm volatile("ldmatrix.sync.aligned.m8n8.x4.shared.b16 {%0,%1,%2,%3}, [%4];"
                 : "=r"(r[0]), "=r"(r[1]), "=r"(r[2]), "=r"(r[3]) : "r"(addr));
}
DINLINE void ldsm_x4t(unsigned* r, unsigned addr) {
    asm volatile("ldmatrix.sync.aligned.m8n8.x4.trans.shared.b16 {%0,%1,%2,%3}, [%4];"
                 : "=r"(r[0]), "=r"(r[1]), "=r"(r[2]), "=r"(r[3]) : "r"(addr));
}

#define CP_ASYNC16(dst, src) \
    asm volatile("cp.async.cg.shared.global [%0], [%1], 16;\n" :: "r"(dst), "l"(src))
#define CP_COMMIT()  asm volatile("cp.async.commit_group;\n")
#define CP_WAIT0()   asm volatile("cp.async.wait_group 0;\n")
#define CP_WAIT1()   asm volatile("cp.async.wait_group 1;\n")

// ============================================================================
// convert: f32 inputs/weights -> bf16 hi/lo global buffers
// ============================================================================
__global__ void __launch_bounds__(256) convert_kernel(
    const float* __restrict__ q, const float* __restrict__ k, const float* __restrict__ v,
    const float* __restrict__ wq, const float* __restrict__ wk,
    const float* __restrict__ wv, const float* __restrict__ wo)
{
    size_t i = ((size_t)blockIdx.x * 256 + threadIdx.x) * 4;
    const float* src;
    __nv_bfloat16 *dh, *dl;
    size_t off;
    if (i < (size_t)3 * XSZ) {
        int z = (int)(i / XSZ);
        off = i - (size_t)z * XSZ;
        src = (z == 0) ? q : (z == 1) ? k : v;
        dh = g_xh + (size_t)z * XSZ; dl = g_xl + (size_t)z * XSZ;
    } else {
        size_t j = i - (size_t)3 * XSZ;
        int z = (int)(j / WSZ);
        off = j - (size_t)z * WSZ;
        src = (z == 0) ? wq : (z == 1) ? wk : (z == 2) ? wv : wo;
        dh = g_wh + (size_t)z * WSZ; dl = g_wl + (size_t)z * WSZ;
    }
    float4 val = *(const float4*)(src + off);
    __nv_bfloat16 h0, l0, h1, l1, h2, l2, h3, l3;
    splitf(val.x, h0, l0); splitf(val.y, h1, l1);
    splitf(val.z, h2, l2); splitf(val.w, h3, l3);
    uint2 uh = { packh(h0, h1), packh(h2, h3) };
    uint2 ul = { packh(l0, l1), packh(l2, l3) };
    *(uint2*)(dh + off) = uh;
    *(uint2*)(dl + off) = ul;
}

// ============================================================================
// GEMM (R8/R15 best): Y = X @ W^T + b, bf16 hi/lo 3-term.
// Tile 128x128, 256 threads, BK=32, 3-stage cp.async, ONE barrier/K-iter,
// XOR-swizzled smem, 2 CTAs/SM. MODE 0 z==0 pre-scales Q output by 1/8.
// ============================================================================
constexpr int G_ARR_B   = 128 * 64;            // 8192 bytes per array
constexpr int G_STAGE_B = 4 * G_ARR_B;         // 32768 bytes per stage
constexpr int GEMM_SMEM = 3 * G_STAGE_B;       // 98304 bytes

template<int MODE>
__global__ void __launch_bounds__(256, 2) gemm_kernel(
    const __nv_bfloat16* __restrict__ Ahg, const __nv_bfloat16* __restrict__ Alg,
    const __nv_bfloat16* __restrict__ Whg, const __nv_bfloat16* __restrict__ Wlg,
    const float* __restrict__ b0p, const float* __restrict__ b1p, const float* __restrict__ b2p,
    __nv_bfloat16* __restrict__ Yh, __nv_bfloat16* __restrict__ Yl,
    float* __restrict__ Yf)
{
    extern __shared__ __nv_bfloat16 gsm[];
    const unsigned smb = smem_u32(gsm);

    const int z = (MODE == 0) ? blockIdx.z : 0;
    const __nv_bfloat16* Ah = Ahg + (size_t)z * XSZ;
    const __nv_bfloat16* Al = Alg + (size_t)z * XSZ;
    const __nv_bfloat16* Bh = Whg + (size_t)z * WSZ;
    const __nv_bfloat16* Bl = Wlg + (size_t)z * WSZ;
    const float* bias = (z == 0) ? b0p : (z == 1) ? b1p : b2p;

    const int t    = threadIdx.x;
    const int w    = t >> 5;
    const int lane = t & 31;
    const int g    = lane >> 2;
    const int tg   = lane & 3;
    const int lm   = lane >> 3;   // ldmatrix matrix id (0..3)
    const int lr   = lane & 7;    // ldmatrix row-in-matrix
    const int wm   = w >> 1;      // 0..3
    const int wn   = w & 1;       // 0..1
    const int m0   = blockIdx.y * 128;
    const int n0   = blockIdx.x * 128;

    unsigned aoff[2], axor[2], boff[4], bxor[4];
    const unsigned aC = (unsigned)(lm >> 1);
    const unsigned bC = (unsigned)(lm & 1);
#pragma unroll
    for (int mi = 0; mi < 2; mi++) {
        int r = wm * 32 + mi * 16 + ((lm & 1) << 3) + lr;
        aoff[mi] = (unsigned)r * 64u;
        axor[mi] = (unsigned)((r >> 1) & 3);
    }
#pragma unroll
    for (int p = 0; p < 4; p++) {
        int r = wn * 64 + p * 16 + ((lm >> 1) << 3) + lr;
        boff[p] = (unsigned)r * 64u;
        bxor[p] = (unsigned)((r >> 1) & 3);
    }

    float acc[2][8][4];
#pragma unroll
    for (int mi = 0; mi < 2; mi++)
#pragma unroll
        for (int ni = 0; ni < 8; ni++)
#pragma unroll
            for (int j = 0; j < 4; j++) acc[mi][ni][j] = 0.f;

    auto issue_stage = [&](int kt, int stg) {
        const unsigned base = (unsigned)(stg * G_STAGE_B);
#pragma unroll
        for (int i = 0; i < 8; i++) {
            int id = t + i * 256;
            int a_ = id >> 9;                 // array 0..3
            int cid = id & 511;
            int row = cid >> 2, c = cid & 3;
            const __nv_bfloat16* gp =
                (a_ == 0) ? Ah : (a_ == 1) ? Al : (a_ == 2) ? Bh : Bl;
            const int r0 = (a_ < 2) ? m0 : n0;
            unsigned dst = smb + base + (unsigned)a_ * G_ARR_B
                         + (unsigned)row * 64u
                         + ((unsigned)(c ^ ((row >> 1) & 3)) << 4);
            CP_ASYNC16(dst, gp + (size_t)(r0 + row) * 1024 + (size_t)kt * 32 + c * 8);
        }
        CP_COMMIT();
    };

    issue_stage(0, 0);
    issue_stage(1, 1);

    for (int kt = 0; kt < 32; kt++) {
        if (kt < 31) CP_WAIT1(); else CP_WAIT0();
        __syncthreads();          // tile kt ready AND compute of kt-1 done

        if (kt + 2 < 32) issue_stage(kt + 2, (kt + 2) % 3);

        const unsigned sb = smb + (unsigned)((kt % 3) * G_STAGE_B);
#pragma unroll
        for (int kk2 = 0; kk2 < 2; kk2++) {
            unsigned ah[2][4], al[2][4], bh[4][4], bl[4][4];
#pragma unroll
            for (int mi = 0; mi < 2; mi++) {
                unsigned cidx = (((unsigned)(2 * kk2) + aC) ^ axor[mi]) << 4;
                ldsm_x4(ah[mi], sb + aoff[mi] + cidx);
                ldsm_x4(al[mi], sb + G_ARR_B + aoff[mi] + cidx);
            }
#pragma unroll
            for (int p = 0; p < 4; p++) {
                unsigned cidx = (((unsigned)(2 * kk2) + bC) ^ bxor[p]) << 4;
                ldsm_x4(bh[p], sb + 2 * G_ARR_B + boff[p] + cidx);
                ldsm_x4(bl[p], sb + 3 * G_ARR_B + boff[p] + cidx);
            }
#pragma unroll
            for (int ni = 0; ni < 8; ni++) {
                const int p = ni >> 1, ix = (ni & 1) * 2;
                unsigned b0h = bh[p][ix], b1h = bh[p][ix + 1];
                unsigned b0l = bl[p][ix], b1l = bl[p][ix + 1];
#pragma unroll
                for (int mi = 0; mi < 2; mi++) {
                    mma16816(acc[mi][ni], ah[mi], b0h, b1h);
                    mma16816(acc[mi][ni], ah[mi], b0l, b1l);
                    mma16816(acc[mi][ni], al[mi], b0h, b1h);
                }
            }
        }
    }

    // ---- epilogue ----
    const size_t zoff = (size_t)z * NQKV;
    const float osc = (MODE == 0 && z == 0) ? 0.125f : 1.0f;  // pre-scale Q
#pragma unroll
    for (int mi = 0; mi < 2; mi++) {
#pragma unroll
        for (int ni = 0; ni < 8; ni++) {
            int r = m0 + wm * 32 + mi * 16 + g;
            int c = n0 + wn * 64 + ni * 8 + tg * 2;
            float b0 = bias[c], b1 = bias[c + 1];
            float v00 = (acc[mi][ni][0] + b0) * osc;
            float v01 = (acc[mi][ni][1] + b1) * osc;
            float v10 = (acc[mi][ni][2] + b0) * osc;
            float v11 = (acc[mi][ni][3] + b1) * osc;
            if (MODE == 0) {
                int bb = r >> 11, ss = r & 2047;
                int hh = c >> 6, d = c & 63;
                size_t i0 = zoff + ((size_t)(bb * H_ + hh) * S_ + ss) * DK_ + d;
                size_t i1 = zoff + ((size_t)(bb * H_ + hh) * S_ + (ss + 8)) * DK_ + d;
                __nv_bfloat16 h0, l0, h1, l1;
                splitf(v00, h0, l0); splitf(v01, h1, l1);
                *(unsigned*)&Yh[i0] = packh(h0, h1);
                *(unsigned*)&Yl[i0] = packh(l0, l1);
                splitf(v10, h0, l0); splitf(v11, h1, l1);
                *(unsigned*)&Yh[i1] = packh(h0, h1);
                *(unsigned*)&Yl[i1] = packh(l0, l1);
            } else {
                Yf[(size_t)r * 1024 + c]           = v00;
                Yf[(size_t)r * 1024 + c + 1]       = v01;
                Yf[(size_t)(r + 8) * 1024 + c]     = v10;
                Yf[(size_t)(r + 8) * 1024 + c + 1] = v11;
            }
        }
    }
}

// ============================================================================
// Flash attention (causal), DK=64, Q-tile 64 (4 warps x 16 rows), KV-tile 64.
// CHANGE vs R15: 128-thread CTAs at 2 CTAs/SM — while one CTA runs softmax/
// barriers, the other's HMMAs fill the tensor pipe. Per-warp work identical.
// Q pre-scaled by 1/8; ktmax = qt+1; mask only on kt==qt.
// ============================================================================
constexpr int ALD = 72;
constexpr int A_ARR = 64 * ALD;         // 4608 elems per array
constexpr int STAGE = 4 * A_ARR;        // Kh,Kl,Vh,Vl
constexpr int ATTN_SMEM = 2 * STAGE * 2;   // 73728 B; x2 CTAs = 147456 <= 228KB

__global__ void __launch_bounds__(128, 2) attn_kernel(
    const __nv_bfloat16* __restrict__ Gh, const __nv_bfloat16* __restrict__ Gl,
    __nv_bfloat16* __restrict__ Ch, __nv_bfloat16* __restrict__ Cl)
{
    extern __shared__ __nv_bfloat16 sm[];

    const int qt   = (int)gridDim.x - 1 - (int)blockIdx.x;  // heavy first
    const int bh   = blockIdx.y;
    const int t    = threadIdx.x;
    const int w    = t >> 5;          // 0..3
    const int lane = t & 31;
    const int g    = lane >> 2;
    const int tg   = lane & 3;
    const int lm   = lane >> 3;
    const int lr   = lane & 7;

    const size_t hb = (size_t)bh * S_ * DK_;
    const __nv_bfloat16* Qhb = Gh + hb;
    const __nv_bfloat16* Qlb = Gl + hb;
    const __nv_bfloat16* Khb = Gh + NQKV + hb;
    const __nv_bfloat16* Klb = Gl + NQKV + hb;
    const __nv_bfloat16* Vhb = Gh + 2 * NQKV + hb;
    const __nv_bfloat16* Vlb = Gl + 2 * NQKV + hb;

    const unsigned smb = smem_u32(sm);
    const float NEG = -1e30f;

    const int kbase = lr * ALD + (lm << 3);
    const int vbase = (((lm & 1) << 3) + lr) * ALD + ((lm >> 1) << 3);

    // ---- Q fragments straight from global (rows qt*64 + w*16 ..) ----
    unsigned qh[4][4], ql[4][4];
    {
        size_t r0 = (size_t)(qt * 64 + w * 16 + g) * DK_;
        size_t r1 = r0 + 8 * DK_;
#pragma unroll
        for (int kk = 0; kk < 4; kk++) {
            int c = kk * 16 + tg * 2;
            qh[kk][0] = *(const unsigned*)&Qhb[r0 + c];
            qh[kk][1] = *(const unsigned*)&Qhb[r1 + c];
            qh[kk][2] = *(const unsigned*)&Qhb[r0 + c + 8];
            qh[kk][3] = *(const unsigned*)&Qhb[r1 + c + 8];
            ql[kk][0] = *(const unsigned*)&Qlb[r0 + c];
            ql[kk][1] = *(const unsigned*)&Qlb[r1 + c];
            ql[kk][2] = *(const unsigned*)&Qlb[r0 + c + 8];
            ql[kk][3] = *(const unsigned*)&Qlb[r1 + c + 8];
        }
    }

    // 2048 16B-chunks per KV tile over 128 threads = 16 per thread
    auto issue_tile = [&](int kt, int stg) {
#pragma unroll
        for (int i = 0; i < 16; i++) {
            int id = t + i * 128;
            int a_ = id >> 9;
            int cid = id & 511;
            int row = cid >> 3, seg = cid & 7;
            const __nv_bfloat16* gp =
                (a_ == 0) ? Khb : (a_ == 1) ? Klb : (a_ == 2) ? Vhb : Vlb;
            unsigned dst = smb + (unsigned)(stg * STAGE + a_ * A_ARR + row * ALD + seg * 8) * 2;
            CP_ASYNC16(dst, gp + (size_t)(kt * 64 + row) * DK_ + seg * 8);
        }
        CP_COMMIT();
    };

    float m0v = NEG, m1v = NEG, l0v = 0.f, l1v = 0.f;
    float o[8][4];
#pragma unroll
    for (int ni = 0; ni < 8; ni++)
#pragma unroll
        for (int j = 0; j < 4; j++) o[ni][j] = 0.f;

    const int ktmax = qt + 1;
    issue_tile(0, 0);

    for (int kt = 0; kt < ktmax; kt++) {
        const int s = kt & 1;
        CP_WAIT0();
        __syncthreads();

        if (kt + 1 < ktmax) issue_tile(kt + 1, s ^ 1);

        const unsigned sb = (unsigned)(s * STAGE);

        // ---- S = Q K^T ----
        float sc_[8][4];
#pragma unroll
        for (int ni = 0; ni < 8; ni++) {
#pragma unroll
            for (int j = 0; j < 4; j++) sc_[ni][j] = 0.f;
            unsigned kh[2][4], kl[2][4];
#pragma unroll
            for (int q = 0; q < 2; q++) {
                unsigned off = sb + ni * 8 * ALD + q * 32 + kbase;
                ldsm_x4(kh[q], smb + off * 2);
                ldsm_x4(kl[q], smb + (off + A_ARR) * 2);
            }
#pragma unroll
            for (int kk = 0; kk < 4; kk++) {
                const int q = kk >> 1, ix = (kk & 1) * 2;
                unsigned b0h = kh[q][ix], b1h = kh[q][ix + 1];
                unsigned b0l = kl[q][ix], b1l = kl[q][ix + 1];
                mma16816(sc_[ni], qh[kk], b0h, b1h);
                mma16816(sc_[ni], qh[kk], b0l, b1l);
                mma16816(sc_[ni], ql[kk], b0h, b1h);
            }
        }

        // ---- causal mask (diagonal tile only; Q pre-scaled) ----
        if (kt == qt) {
            const int rA = w * 16 + g;       // row within tile
            const int rB = rA + 8;
#pragma unroll
            for (int ni = 0; ni < 8; ni++) {
                int c0 = ni * 8 + tg * 2;    // col within tile
                if (c0     > rA) sc_[ni][0] = NEG;
                if (c0 + 1 > rA) sc_[ni][1] = NEG;
                if (c0     > rB) sc_[ni][2] = NEG;
                if (c0 + 1 > rB) sc_[ni][3] = NEG;
            }
        }

        // ---- streaming softmax ----
        float mx0 = NEG, mx1 = NEG;
#pragma unroll
        for (int ni = 0; ni < 8; ni++) {
            mx0 = fmaxf(mx0, fmaxf(sc_[ni][0], sc_[ni][1]));
            mx1 = fmaxf(mx1, fmaxf(sc_[ni][2], sc_[ni][3]));
        }
        mx0 = fmaxf(mx0, __shfl_xor_sync(0xffffffffu, mx0, 1));
        mx0 = fmaxf(mx0, __shfl_xor_sync(0xffffffffu, mx0, 2));
        mx1 = fmaxf(mx1, __shfl_xor_sync(0xffffffffu, mx1, 1));
        mx1 = fmaxf(mx1, __shfl_xor_sync(0xffffffffu, mx1, 2));

        float nm0 = fmaxf(m0v, mx0), nm1 = fmaxf(m1v, mx1);
        float corr0 = __expf(m0v - nm0), corr1 = __expf(m1v - nm1);

        float sum0 = 0.f, sum1 = 0.f;
#pragma unroll
        for (int ni = 0; ni < 8; ni++) {
            sc_[ni][0] = __expf(sc_[ni][0] - nm0);
            sc_[ni][1] = __expf(sc_[ni][1] - nm0);
            sc_[ni][2] = __expf(sc_[ni][2] - nm1);
            sc_[ni][3] = __expf(sc_[ni][3] - nm1);
            sum0 += sc_[ni][0] + sc_[ni][1];
            sum1 += sc_[ni][2] + sc_[ni][3];
        }
        sum0 += __shfl_xor_sync(0xffffffffu, sum0, 1);
        sum0 += __shfl_xor_sync(0xffffffffu, sum0, 2);
        sum1 += __shfl_xor_sync(0xffffffffu, sum1, 1);
        sum1 += __shfl_xor_sync(0xffffffffu, sum1, 2);

        l0v = l0v * corr0 + sum0;
        l1v = l1v * corr1 + sum1;
        m0v = nm0; m1v = nm1;

#pragma unroll
        for (int ni = 0; ni < 8; ni++) {
            o[ni][0] *= corr0; o[ni][1] *= corr0;
            o[ni][2] *= corr1; o[ni][3] *= corr1;
        }

        // ---- O += P V ----
#pragma unroll
        for (int j = 0; j < 4; j++) {
            unsigned ah[4], al[4];
            {
                __nv_bfloat16 h0, l0, h1, l1;
                splitf(sc_[2 * j][0], h0, l0); splitf(sc_[2 * j][1], h1, l1);
                ah[0] = packh(h0, h1); al[0] = packh(l0, l1);
                splitf(sc_[2 * j][2], h0, l0); splitf(sc_[2 * j][3], h1, l1);
                ah[1] = packh(h0, h1); al[1] = packh(l0, l1);
                splitf(sc_[2 * j + 1][0], h0, l0); splitf(sc_[2 * j + 1][1], h1, l1);
                ah[2] = packh(h0, h1); al[2] = packh(l0, l1);
                splitf(sc_[2 * j + 1][2], h0, l0); splitf(sc_[2 * j + 1][3], h1, l1);
                ah[3] = packh(h0, h1); al[3] = packh(l0, l1);
            }
            unsigned vh[4][4], vl[4][4];
#pragma unroll
            for (int p = 0; p < 4; p++) {
                unsigned off = sb + 2 * A_ARR + j * 16 * ALD + p * 16 + vbase;
                ldsm_x4t(vh[p], smb + off * 2);
                ldsm_x4t(vl[p], smb + (off + A_ARR) * 2);
            }
#pragma unroll
            for (int ni = 0; ni < 8; ni++) {
                const int p = ni >> 1, ix = (ni & 1) * 2;
                unsigned b0h = vh[p][ix], b1h = vh[p][ix + 1];
                unsigned b0l = vl[p][ix], b1l = vl[p][ix + 1];
                mma16816(o[ni], ah, b0h, b1h);
                mma16816(o[ni], ah, b0l, b1l);
                mma16816(o[ni], al, b0h, b1h);
            }
        }
    }

    // ---- finalize -> hi/lo bf16 context ----
    float inv0 = 1.f / l0v, inv1 = 1.f / l1v;
    int bb = bh >> 4, hh = bh & 15;
    int q0 = qt * 64 + w * 16 + g;
#pragma unroll
    for (int ni = 0; ni < 8; ni++) {
        int d = ni * 8 + tg * 2;
        size_t i0 = ((size_t)(bb * S_ + q0)) * D_ + hh * 64 + d;
        size_t i1 = ((size_t)(bb * S_ + q0 + 8)) * D_ + hh * 64 + d;
        __nv_bfloat16 h0, l0, h1, l1;
        splitf(o[ni][0] * inv0, h0, l0); splitf(o[ni][1] * inv0, h1, l1);
        *(unsigned*)&Ch[i0] = packh(h0, h1);
        *(unsigned*)&Cl[i0] = packh(l0, l1);
        splitf(o[ni][2] * inv1, h0, l0); splitf(o[ni][3] * inv1, h1, l1);
        *(unsigned*)&Ch[i1] = packh(h0, h1);
        *(unsigned*)&Cl[i1] = packh(l0, l1);
    }
}

// ============================================================================
// Launch
// ============================================================================
extern "C" void kernel_launch(void* const* d_in, const int* in_sizes, int n_in,
                              void* d_out, int out_size)
{
    const float* q  = (const float*)d_in[0];
    const float* k  = (const float*)d_in[1];
    const float* v  = (const float*)d_in[2];
    const float* wq = (const float*)d_in[4];
    const float* bq = (const float*)d_in[5];
    const float* wk = (const float*)d_in[6];
    const float* bk = (const float*)d_in[7];
    const float* wv = (const float*)d_in[8];
    const float* bv = (const float*)d_in[9];
    const float* wo = (const float*)d_in[10];
    const float* bo = (const float*)d_in[11];
    float* out = (float*)d_out;

    __nv_bfloat16 *gxh, *gxl, *gwh, *gwl, *gh, *gl, *gch, *gcl;
    cudaGetSymbolAddress((void**)&gxh, g_xh);
    cudaGetSymbolAddress((void**)&gxl, g_xl);
    cudaGetSymbolAddress((void**)&gwh, g_wh);
    cudaGetSymbolAddress((void**)&gwl, g_wl);
    cudaGetSymbolAddress((void**)&gh,  g_h);
    cudaGetSymbolAddress((void**)&gl,  g_l);
    cudaGetSymbolAddress((void**)&gch, g_ch);
    cudaGetSymbolAddress((void**)&gcl, g_cl);

    cudaFuncSetAttribute(gemm_kernel<0>,
                         cudaFuncAttributeMaxDynamicSharedMemorySize, GEMM_SMEM);
    cudaFuncSetAttribute(gemm_kernel<1>,
                         cudaFuncAttributeMaxDynamicSharedMemorySize, GEMM_SMEM);
    cudaFuncSetAttribute(attn_kernel,
                         cudaFuncAttributeMaxDynamicSharedMemorySize, ATTN_SMEM);

    // 1) split inputs + weights to bf16 hi/lo
    convert_kernel<<<16384, 256>>>(q, k, v, wq, wk, wv, wo);

    // 2) QKV projections (Q output pre-scaled by 1/8)
    gemm_kernel<0><<<dim3(8, 32, 3), 256, GEMM_SMEM>>>(
        gxh, gxl, gwh, gwl, bq, bk, bv, gh, gl, nullptr);

    // 3) attention (128-thread CTAs, Q-tile 64, 2 CTAs/SM)
    attn_kernel<<<dim3(S_ / 64, B_ * H_), 128, ATTN_SMEM>>>(gh, gl, gch, gcl);

    // 4) output projection
    gemm_kernel<1><<<dim3(8, 32, 1), 256, GEMM_SMEM>>>(
        gch, gcl, gwh + 3 * WSZ, gwl + 3 * WSZ, bo, bo, bo, nullptr, nullptr, out);
}